// round 6
// baseline (speedup 1.0000x reference)
#include <cuda_runtime.h>
#include <math.h>
#include <stdint.h>

#define D   128
#define NN  30000
#define NE  480000
#define NL  4
#define EPSV 1e-7f

// ---------------- device scratch (static, no allocation) ----------------
__device__ float g_h[NN * D];     // current node features
__device__ float g_out[NN * D];   // post-aggregation (agg + residual)
__device__ int   g_srcs[NE];      // CSR-ordered source node per edge
__device__ float g_attrs[NE];     // CSR-ordered edge attr scalar per edge
__device__ int   g_eids[NE];      // CSR-ordered original edge ids (determinism sort key)
__device__ int   g_row[NN + 1];   // CSR row offsets
__device__ int   g_cur[NN];       // histogram / scatter cursor

// ---------------- CSR build ----------------
__global__ void k_zero() {
    int i = blockIdx.x * blockDim.x + threadIdx.x;
    if (i < NN) g_cur[i] = 0;
}

__global__ void k_hist(const int* __restrict__ dst) {
    int e = blockIdx.x * blockDim.x + threadIdx.x;
    if (e < NE) atomicAdd(&g_cur[dst[e]], 1);
}

// single-block exclusive scan of g_cur -> g_row, also reset g_cur to row start (cursor)
__global__ void k_scan() {
    __shared__ int ssum[1024];
    int t = threadIdx.x;
    const int CH = (NN + 1023) / 1024;  // 30
    int base = t * CH;
    int s = 0;
    for (int i = 0; i < CH; i++) {
        int idx = base + i;
        if (idx < NN) s += g_cur[idx];
    }
    ssum[t] = s;
    __syncthreads();
    for (int off = 1; off < 1024; off <<= 1) {
        int v = (t >= off) ? ssum[t - off] : 0;
        __syncthreads();
        ssum[t] += v;
        __syncthreads();
    }
    int run = (t == 0) ? 0 : ssum[t - 1];
    for (int i = 0; i < CH; i++) {
        int idx = base + i;
        if (idx < NN) {
            int c = g_cur[idx];
            g_row[idx] = run;
            g_cur[idx] = run;
            run += c;
        }
    }
    if (t == 1023) g_row[NN] = run;
}

__global__ void k_scatter(const int* __restrict__ src, const int* __restrict__ dst,
                          const float* __restrict__ attr) {
    int e = blockIdx.x * blockDim.x + threadIdx.x;
    if (e >= NE) return;
    int d = dst[e];
    int pos = atomicAdd(&g_cur[d], 1);
    g_eids[pos]  = e;
    g_srcs[pos]  = src[e];
    g_attrs[pos] = attr[e];
}

// per-node insertion sort by edge id -> deterministic reduction order
__global__ void k_sort() {
    int v = blockIdx.x * blockDim.x + threadIdx.x;
    if (v >= NN) return;
    int s = g_row[v], e = g_row[v + 1];
    for (int i = s + 1; i < e; i++) {
        int   key = g_eids[i];
        int   sr  = g_srcs[i];
        float at  = g_attrs[i];
        int j = i - 1;
        while (j >= s && g_eids[j] > key) {
            g_eids[j + 1]  = g_eids[j];
            g_srcs[j + 1]  = g_srcs[j];
            g_attrs[j + 1] = g_attrs[j];
            j--;
        }
        g_eids[j + 1]  = key;
        g_srcs[j + 1]  = sr;
        g_attrs[j + 1] = at;
    }
}

// ---------------- node encoder stage 1: h1 = relu(x @ Wn1 + bn1) ----------------
__global__ void k_enc1(const float* __restrict__ x, const float* __restrict__ Wn1,
                       const float* __restrict__ bn1) {
    int v = blockIdx.x;
    int c = threadIdx.x;
    __shared__ float sx[7];
    if (c < 7) sx[c] = x[v * 7 + c];
    __syncthreads();
    float acc = bn1[c];
#pragma unroll
    for (int k = 0; k < 7; k++) acc += sx[k] * Wn1[k * D + c];
    g_out[v * D + c] = fmaxf(acc, 0.f);
}

// ---------------- tensor-core 64x128 Linear (3xTF32): C = A @ W + b ----------------
// Tile shrunk from 128x128 to 64x128: acc regs 64->32 so >=2 CTAs/SM (R5 showed
// regs=137 -> 1 CTA/SM -> occ 12.4%, phase serialization).
__device__ __forceinline__ uint32_t f2tf32(float x) {
    uint32_t r;
    asm("cvt.rna.tf32.f32 %0, %1;" : "=r"(r) : "f"(x));
    return r;
}
__device__ __forceinline__ void mma_tf32(float* c, const uint32_t* a, const uint32_t* b) {
    asm volatile(
        "mma.sync.aligned.m16n8k8.row.col.f32.tf32.tf32.f32 "
        "{%0,%1,%2,%3}, {%4,%5,%6,%7}, {%8,%9}, {%0,%1,%2,%3};"
        : "+f"(c[0]), "+f"(c[1]), "+f"(c[2]), "+f"(c[3])
        : "r"(a[0]), "r"(a[1]), "r"(a[2]), "r"(a[3]), "r"(b[0]), "r"(b[1]));
}

#define GK 16   // K chunk
#define TM 64   // rows per block

__global__ __launch_bounds__(256, 2) void k_gemm_tc(const float* __restrict__ A,
                                                    const float* __restrict__ W,
                                                    const float* __restrict__ b,
                                                    float* __restrict__ C) {
    // padded strides for conflict-free fragment LDS (136%32=8; 20 -> g*20+t4 unique)
    __shared__ float sWh[GK][136], sWl[GK][136];
    __shared__ float sAh[TM][20], sAl[TM][20];
    int tid  = threadIdx.x;          // 256
    int w    = tid >> 5;             // warp 0..7: owns n-slice [w*16, w*16+16)
    int lane = tid & 31;
    int g    = lane >> 2;            // 0..7
    int t4   = lane & 3;             // 0..3
    int rowbase = blockIdx.x * TM;
    int n0 = w * 16;

    float acc[4][2][4];
#pragma unroll
    for (int mt = 0; mt < 4; mt++)
#pragma unroll
        for (int nt = 0; nt < 2; nt++)
#pragma unroll
            for (int i = 0; i < 4; i++) acc[mt][nt][i] = 0.f;

    for (int kc = 0; kc < D; kc += GK) {
        // stage W chunk [GK x 128] as tf32 hi/lo: 512 float4, 2 per thread
#pragma unroll
        for (int i = tid; i < 512; i += 256) {
            int r = i >> 5, c4 = i & 31;
            float4 wv = ((const float4*)(W + (kc + r) * D))[c4];
            float4 hi, lo;
            hi.x = __uint_as_float(f2tf32(wv.x)); lo.x = __uint_as_float(f2tf32(wv.x - hi.x));
            hi.y = __uint_as_float(f2tf32(wv.y)); lo.y = __uint_as_float(f2tf32(wv.y - hi.y));
            hi.z = __uint_as_float(f2tf32(wv.z)); lo.z = __uint_as_float(f2tf32(wv.z - hi.z));
            hi.w = __uint_as_float(f2tf32(wv.w)); lo.w = __uint_as_float(f2tf32(wv.w - hi.w));
            *(float4*)&sWh[r][c4 * 4] = hi;
            *(float4*)&sWl[r][c4 * 4] = lo;
        }
        // stage A chunk [TM x GK] as tf32 hi/lo: 256 float4, 1 per thread
        {
            int i = tid;
            int r = i >> 2, c4 = i & 3;
            int gr = rowbase + r;
            float4 av = (gr < NN) ? ((const float4*)(A + gr * D + kc))[c4]
                                  : make_float4(0.f, 0.f, 0.f, 0.f);
            float4 hi, lo;
            hi.x = __uint_as_float(f2tf32(av.x)); lo.x = __uint_as_float(f2tf32(av.x - hi.x));
            hi.y = __uint_as_float(f2tf32(av.y)); lo.y = __uint_as_float(f2tf32(av.y - hi.y));
            hi.z = __uint_as_float(f2tf32(av.z)); lo.z = __uint_as_float(f2tf32(av.z - hi.z));
            hi.w = __uint_as_float(f2tf32(av.w)); lo.w = __uint_as_float(f2tf32(av.w - hi.w));
            *(float4*)&sAh[r][c4 * 4] = hi;
            *(float4*)&sAl[r][c4 * 4] = lo;
        }
        __syncthreads();

#pragma unroll
        for (int kt = 0; kt < GK / 8; kt++) {
            int k8 = kt * 8;
            uint32_t bh[2][2], bl[2][2];
#pragma unroll
            for (int nt = 0; nt < 2; nt++) {
                int n = n0 + nt * 8 + g;
                bh[nt][0] = __float_as_uint(sWh[k8 + t4][n]);
                bh[nt][1] = __float_as_uint(sWh[k8 + t4 + 4][n]);
                bl[nt][0] = __float_as_uint(sWl[k8 + t4][n]);
                bl[nt][1] = __float_as_uint(sWl[k8 + t4 + 4][n]);
            }
#pragma unroll
            for (int mt = 0; mt < 4; mt++) {
                int r0 = mt * 16 + g;
                uint32_t ah[4], al[4];
                ah[0] = __float_as_uint(sAh[r0][k8 + t4]);
                ah[1] = __float_as_uint(sAh[r0 + 8][k8 + t4]);
                ah[2] = __float_as_uint(sAh[r0][k8 + t4 + 4]);
                ah[3] = __float_as_uint(sAh[r0 + 8][k8 + t4 + 4]);
                al[0] = __float_as_uint(sAl[r0][k8 + t4]);
                al[1] = __float_as_uint(sAl[r0 + 8][k8 + t4]);
                al[2] = __float_as_uint(sAl[r0][k8 + t4 + 4]);
                al[3] = __float_as_uint(sAl[r0 + 8][k8 + t4 + 4]);
#pragma unroll
                for (int nt = 0; nt < 2; nt++) {
                    mma_tf32(acc[mt][nt], al, bh[nt]);  // small terms first
                    mma_tf32(acc[mt][nt], ah, bl[nt]);
                    mma_tf32(acc[mt][nt], ah, bh[nt]);
                }
            }
        }
        __syncthreads();
    }

#pragma unroll
    for (int mt = 0; mt < 4; mt++) {
#pragma unroll
        for (int nt = 0; nt < 2; nt++) {
            int n = n0 + nt * 8 + t4 * 2;
            float2 bb = *(const float2*)&b[n];
            int r = rowbase + mt * 16 + g;
            if (r < NN) {
                float2 o = make_float2(acc[mt][nt][0] + bb.x, acc[mt][nt][1] + bb.y);
                *(float2*)&C[r * D + n] = o;
            }
            int r2 = r + 8;
            if (r2 < NN) {
                float2 o = make_float2(acc[mt][nt][2] + bb.x, acc[mt][nt][3] + bb.y);
                *(float2*)&C[r2 * D + n] = o;
            }
        }
    }
}

// ---------------- GENConv aggregation ----------------
// One block (128 threads) per node, one thread per channel.
// Edge list staged in smem. Gathers batched 8 at a time (independent loads,
// MLP=8) BEFORE the dependent online-softmax chain -> removes the serial
// ~250-cycle L2 stall per edge that R5's version paid.
__global__ void k_agg(const float* __restrict__ We, const float* __restrict__ be) {
    int v = blockIdx.x;
    int c = threadIdx.x;
    __shared__ int   s_src[128];
    __shared__ float s_attr[128];
    int s = g_row[v], e = g_row[v + 1];
    float we_c = We[c], be_c = be[c];
    float m = -1e30f, den = 0.f, ws = 0.f;
    for (int base = s; base < e; base += 128) {
        int n = min(128, e - base);
        if (c < n) {
            s_src[c]  = g_srcs[base + c];
            s_attr[c] = g_attrs[base + c];
        }
        __syncthreads();
        for (int i = 0; i < n; i += 8) {
            float hv[8];
#pragma unroll
            for (int j = 0; j < 8; j++) {
                int idx = i + j;
                hv[j] = (idx < n) ? g_h[s_src[idx] * D + c] : 0.f;
            }
#pragma unroll
            for (int j = 0; j < 8; j++) {
                int idx = i + j;
                if (idx < n) {
                    float msg = fmaxf(hv[j] + s_attr[idx] * we_c + be_c, 0.f) + EPSV;
                    float d   = msg - m;
                    float t   = __expf(-fabsf(d));  // single exp: exp(min-max)
                    bool  up  = d > 0.f;
                    float nden = up ? den * t + 1.f : den + t;
                    float nws  = up ? ws  * t + msg : ws + t * msg;
                    m   = up ? msg : m;
                    den = nden;
                    ws  = nws;
                }
            }
        }
        __syncthreads();
    }
    float agg = (e > s) ? (ws / den) : 0.f;
    g_out[v * D + c] = agg + g_h[v * D + c];
}

// ---------------- output head: out = h @ Wo + bo, one warp per node ----------------
__global__ void k_head(const float* __restrict__ Wo, const float* __restrict__ bo,
                       float* __restrict__ out) {
    int gw   = (blockIdx.x * blockDim.x + threadIdx.x) >> 5;
    int lane = threadIdx.x & 31;
    if (gw >= NN) return;
    float h0 = g_h[gw * D + lane];
    float h1 = g_h[gw * D + lane + 32];
    float h2 = g_h[gw * D + lane + 64];
    float h3 = g_h[gw * D + lane + 96];
#pragma unroll
    for (int o = 0; o < 3; o++) {
        float acc = h0 * __ldg(&Wo[lane * 3 + o]) + h1 * __ldg(&Wo[(lane + 32) * 3 + o]) +
                    h2 * __ldg(&Wo[(lane + 64) * 3 + o]) + h3 * __ldg(&Wo[(lane + 96) * 3 + o]);
#pragma unroll
        for (int off = 16; off; off >>= 1) acc += __shfl_down_sync(0xffffffff, acc, off);
        if (lane == 0) out[gw * 3 + o] = acc + bo[o];
    }
}

// ---------------- launch (first k_gemm_tc kept at launch idx 3 = profiled slot) ----
extern "C" void kernel_launch(void* const* d_in, const int* in_sizes, int n_in,
                              void* d_out, int out_size) {
    const float* x    = (const float*)d_in[0];
    const int*   ei   = (const int*)d_in[1];   // [2, NE]
    const float* attr = (const float*)d_in[2];
    const float* Wn1  = (const float*)d_in[3];
    const float* bn1  = (const float*)d_in[4];
    const float* Wn2  = (const float*)d_in[5];
    const float* bn2  = (const float*)d_in[6];
    const float* We   = (const float*)d_in[7];
    const float* be   = (const float*)d_in[8];
    const float* Wg   = (const float*)d_in[9];  // [4,128,128]
    const float* bg   = (const float*)d_in[10]; // [4,128]
    const float* Wo   = (const float*)d_in[11];
    const float* bo   = (const float*)d_in[12];
    float* out = (float*)d_out;

    const int* src = ei;
    const int* dst = ei + NE;

    float* p_h;
    float* p_out;
    cudaGetSymbolAddress((void**)&p_h, g_h);
    cudaGetSymbolAddress((void**)&p_out, g_out);

    int gblocks = (NN + TM - 1) / TM;

    // idx 0: encoder stage 1 (independent of CSR)
    k_enc1<<<NN, D>>>(x, Wn1, bn1);                    // g_out = relu(x@Wn1+bn1)
    // idx 1-2: CSR build start
    k_zero<<<(NN + 255) / 256, 256>>>();
    k_hist<<<(NE + 255) / 256, 256>>>(dst);
    // idx 3: encoder GEMM  <-- profiled slot
    k_gemm_tc<<<gblocks, 256>>>(p_out, Wn2, bn2, p_h); // g_h = g_out@Wn2+bn2
    // idx 4-6: CSR build finish
    k_scan<<<1, 1024>>>();
    k_scatter<<<(NE + 255) / 256, 256>>>(src, dst, attr);
    k_sort<<<(NN + 255) / 256, 256>>>();

    // ---- 4 GENConv layers ----
    for (int l = 0; l < NL; l++) {
        k_agg<<<NN, D>>>(We, be);                                        // g_out = agg + g_h
        k_gemm_tc<<<gblocks, 256>>>(p_out, Wg + l * D * D, bg + l * D, p_h);
    }

    // ---- head ----
    k_head<<<(NN * 32 + 255) / 256, 256>>>(Wo, bo, out);
}

// round 7
// speedup vs baseline: 1.0993x; 1.0993x over previous
#include <cuda_runtime.h>
#include <math.h>
#include <stdint.h>

#define D   128
#define NN  30000
#define NE  480000
#define NL  4
#define EPSV 1e-7f

// ---------------- device scratch (static, no allocation) ----------------
__device__ float g_h[NN * D];     // current node features
__device__ float g_out[NN * D];   // post-aggregation (agg + residual)
__device__ int   g_srcs[NE];      // CSR-ordered source node per edge
__device__ float g_attrs[NE];     // CSR-ordered edge attr scalar per edge
__device__ int   g_eids[NE];      // CSR-ordered original edge ids (determinism sort key)
__device__ int   g_row[NN + 1];   // CSR row offsets
__device__ int   g_cur[NN];       // histogram / scatter cursor
// preconverted tf32 hi/lo weights: slot 0 = Wn2, slots 1..4 = Wg[0..3]
__device__ float g_Wh[(NL + 1) * D * D];
__device__ float g_Wl[(NL + 1) * D * D];

// ---------------- CSR build ----------------
__global__ void k_zero() {
    int i = blockIdx.x * blockDim.x + threadIdx.x;
    if (i < NN) g_cur[i] = 0;
}

__global__ void k_hist(const int* __restrict__ dst) {
    int e = blockIdx.x * blockDim.x + threadIdx.x;
    if (e < NE) atomicAdd(&g_cur[dst[e]], 1);
}

// single-block exclusive scan of g_cur -> g_row, also reset g_cur to row start (cursor)
__global__ void k_scan() {
    __shared__ int ssum[1024];
    int t = threadIdx.x;
    const int CH = (NN + 1023) / 1024;  // 30
    int base = t * CH;
    int s = 0;
    for (int i = 0; i < CH; i++) {
        int idx = base + i;
        if (idx < NN) s += g_cur[idx];
    }
    ssum[t] = s;
    __syncthreads();
    for (int off = 1; off < 1024; off <<= 1) {
        int v = (t >= off) ? ssum[t - off] : 0;
        __syncthreads();
        ssum[t] += v;
        __syncthreads();
    }
    int run = (t == 0) ? 0 : ssum[t - 1];
    for (int i = 0; i < CH; i++) {
        int idx = base + i;
        if (idx < NN) {
            int c = g_cur[idx];
            g_row[idx] = run;
            g_cur[idx] = run;
            run += c;
        }
    }
    if (t == 1023) g_row[NN] = run;
}

__global__ void k_scatter(const int* __restrict__ src, const int* __restrict__ dst,
                          const float* __restrict__ attr) {
    int e = blockIdx.x * blockDim.x + threadIdx.x;
    if (e >= NE) return;
    int d = dst[e];
    int pos = atomicAdd(&g_cur[d], 1);
    g_eids[pos]  = e;
    g_srcs[pos]  = src[e];
    g_attrs[pos] = attr[e];
}

// per-node insertion sort by edge id -> deterministic reduction order
__global__ void k_sort() {
    int v = blockIdx.x * blockDim.x + threadIdx.x;
    if (v >= NN) return;
    int s = g_row[v], e = g_row[v + 1];
    for (int i = s + 1; i < e; i++) {
        int   key = g_eids[i];
        int   sr  = g_srcs[i];
        float at  = g_attrs[i];
        int j = i - 1;
        while (j >= s && g_eids[j] > key) {
            g_eids[j + 1]  = g_eids[j];
            g_srcs[j + 1]  = g_srcs[j];
            g_attrs[j + 1] = g_attrs[j];
            j--;
        }
        g_eids[j + 1]  = key;
        g_srcs[j + 1]  = sr;
        g_attrs[j + 1] = at;
    }
}

// ---------------- node encoder stage 1: h1 = relu(x @ Wn1 + bn1) ----------------
__global__ void k_enc1(const float* __restrict__ x, const float* __restrict__ Wn1,
                       const float* __restrict__ bn1) {
    int v = blockIdx.x;
    int c = threadIdx.x;
    __shared__ float sx[7];
    if (c < 7) sx[c] = x[v * 7 + c];
    __syncthreads();
    float acc = bn1[c];
#pragma unroll
    for (int k = 0; k < 7; k++) acc += sx[k] * Wn1[k * D + c];
    g_out[v * D + c] = fmaxf(acc, 0.f);
}

// ---------------- weight preconversion: W -> tf32 hi/lo (once per launch) -------
__device__ __forceinline__ uint32_t f2tf32(float x) {
    uint32_t r;
    asm("cvt.rna.tf32.f32 %0, %1;" : "=r"(r) : "f"(x));
    return r;
}

__global__ void k_prepW(const float* __restrict__ Wn2, const float* __restrict__ Wg) {
    int i = blockIdx.x * blockDim.x + threadIdx.x;  // (NL+1)*D*D = 81920
    if (i >= (NL + 1) * D * D) return;
    int m = i / (D * D);
    int j = i - m * D * D;
    float w = (m == 0) ? Wn2[j] : Wg[(m - 1) * D * D + j];
    float hi = __uint_as_float(f2tf32(w));
    g_Wh[i] = hi;
    g_Wl[i] = __uint_as_float(f2tf32(w - hi));
}

// ---------------- tensor-core 64x128 Linear (3xTF32): C = A @ W + b ----------------
// W arrives preconverted (g_Wh/g_Wl): staging is pure float4 copies (R6 showed
// per-block W cvt = the dominant ALU overhead, redundant x469 blocks).
__device__ __forceinline__ void mma_tf32(float* c, const uint32_t* a, const uint32_t* b) {
    asm volatile(
        "mma.sync.aligned.m16n8k8.row.col.f32.tf32.tf32.f32 "
        "{%0,%1,%2,%3}, {%4,%5,%6,%7}, {%8,%9}, {%0,%1,%2,%3};"
        : "+f"(c[0]), "+f"(c[1]), "+f"(c[2]), "+f"(c[3])
        : "r"(a[0]), "r"(a[1]), "r"(a[2]), "r"(a[3]), "r"(b[0]), "r"(b[1]));
}

#define GK 16   // K chunk
#define TM 64   // rows per block

__global__ __launch_bounds__(256, 2) void k_gemm_tc(const float* __restrict__ A,
                                                    const float* __restrict__ Wh,
                                                    const float* __restrict__ Wl,
                                                    const float* __restrict__ b,
                                                    float* __restrict__ C) {
    // padded strides for conflict-free fragment LDS (136%32=8; 20 -> g*20+t4 unique)
    __shared__ float sWh[GK][136], sWl[GK][136];
    __shared__ float sAh[TM][20], sAl[TM][20];
    int tid  = threadIdx.x;          // 256
    int w    = tid >> 5;             // warp 0..7: owns n-slice [w*16, w*16+16)
    int lane = tid & 31;
    int g    = lane >> 2;            // 0..7
    int t4   = lane & 3;             // 0..3
    int rowbase = blockIdx.x * TM;
    int n0 = w * 16;

    float acc[4][2][4];
#pragma unroll
    for (int mt = 0; mt < 4; mt++)
#pragma unroll
        for (int nt = 0; nt < 2; nt++)
#pragma unroll
            for (int i = 0; i < 4; i++) acc[mt][nt][i] = 0.f;

    for (int kc = 0; kc < D; kc += GK) {
        // stage W chunk [GK x 128] hi/lo: pure copies, 512 float4 each
#pragma unroll
        for (int i = tid; i < 512; i += 256) {
            int r = i >> 5, c4 = i & 31;
            *(float4*)&sWh[r][c4 * 4] = ((const float4*)(Wh + (kc + r) * D))[c4];
            *(float4*)&sWl[r][c4 * 4] = ((const float4*)(Wl + (kc + r) * D))[c4];
        }
        // stage A chunk [TM x GK] as tf32 hi/lo: 256 float4, 1 per thread
        {
            int i = tid;
            int r = i >> 2, c4 = i & 3;
            int gr = rowbase + r;
            float4 av = (gr < NN) ? ((const float4*)(A + gr * D + kc))[c4]
                                  : make_float4(0.f, 0.f, 0.f, 0.f);
            float4 hi, lo;
            hi.x = __uint_as_float(f2tf32(av.x)); lo.x = __uint_as_float(f2tf32(av.x - hi.x));
            hi.y = __uint_as_float(f2tf32(av.y)); lo.y = __uint_as_float(f2tf32(av.y - hi.y));
            hi.z = __uint_as_float(f2tf32(av.z)); lo.z = __uint_as_float(f2tf32(av.z - hi.z));
            hi.w = __uint_as_float(f2tf32(av.w)); lo.w = __uint_as_float(f2tf32(av.w - hi.w));
            *(float4*)&sAh[r][c4 * 4] = hi;
            *(float4*)&sAl[r][c4 * 4] = lo;
        }
        __syncthreads();

#pragma unroll
        for (int kt = 0; kt < GK / 8; kt++) {
            int k8 = kt * 8;
            uint32_t bh[2][2], bl[2][2];
#pragma unroll
            for (int nt = 0; nt < 2; nt++) {
                int n = n0 + nt * 8 + g;
                bh[nt][0] = __float_as_uint(sWh[k8 + t4][n]);
                bh[nt][1] = __float_as_uint(sWh[k8 + t4 + 4][n]);
                bl[nt][0] = __float_as_uint(sWl[k8 + t4][n]);
                bl[nt][1] = __float_as_uint(sWl[k8 + t4 + 4][n]);
            }
#pragma unroll
            for (int mt = 0; mt < 4; mt++) {
                int r0 = mt * 16 + g;
                uint32_t ah[4], al[4];
                ah[0] = __float_as_uint(sAh[r0][k8 + t4]);
                ah[1] = __float_as_uint(sAh[r0 + 8][k8 + t4]);
                ah[2] = __float_as_uint(sAh[r0][k8 + t4 + 4]);
                ah[3] = __float_as_uint(sAh[r0 + 8][k8 + t4 + 4]);
                al[0] = __float_as_uint(sAl[r0][k8 + t4]);
                al[1] = __float_as_uint(sAl[r0 + 8][k8 + t4]);
                al[2] = __float_as_uint(sAl[r0][k8 + t4 + 4]);
                al[3] = __float_as_uint(sAl[r0 + 8][k8 + t4 + 4]);
#pragma unroll
                for (int nt = 0; nt < 2; nt++) {
                    mma_tf32(acc[mt][nt], al, bh[nt]);  // small terms first
                    mma_tf32(acc[mt][nt], ah, bl[nt]);
                    mma_tf32(acc[mt][nt], ah, bh[nt]);
                }
            }
        }
        __syncthreads();
    }

#pragma unroll
    for (int mt = 0; mt < 4; mt++) {
#pragma unroll
        for (int nt = 0; nt < 2; nt++) {
            int n = n0 + nt * 8 + t4 * 2;
            float2 bb = *(const float2*)&b[n];
            int r = rowbase + mt * 16 + g;
            if (r < NN) {
                float2 o = make_float2(acc[mt][nt][0] + bb.x, acc[mt][nt][1] + bb.y);
                *(float2*)&C[r * D + n] = o;
            }
            int r2 = r + 8;
            if (r2 < NN) {
                float2 o = make_float2(acc[mt][nt][2] + bb.x, acc[mt][nt][3] + bb.y);
                *(float2*)&C[r2 * D + n] = o;
            }
        }
    }
}

// ---------------- GENConv aggregation (R5 version — proven fastest) ----------------
// One block (128 threads) per node, one thread per channel.
// Edge list staged in smem; online softmax with a SINGLE exp per edge.
__global__ void k_agg(const float* __restrict__ We, const float* __restrict__ be) {
    int v = blockIdx.x;
    int c = threadIdx.x;
    __shared__ int   s_src[128];
    __shared__ float s_attr[128];
    int s = g_row[v], e = g_row[v + 1];
    float we_c = We[c], be_c = be[c];
    float m = -1e30f, den = 0.f, ws = 0.f;
    for (int base = s; base < e; base += 128) {
        int n = min(128, e - base);
        if (c < n) {
            s_src[c]  = g_srcs[base + c];
            s_attr[c] = g_attrs[base + c];
        }
        __syncthreads();
        for (int i = 0; i < n; i++) {
            float hv  = g_h[s_src[i] * D + c];
            float msg = fmaxf(hv + s_attr[i] * we_c + be_c, 0.f) + EPSV;
            float d   = msg - m;
            float t   = __expf(-fabsf(d));  // exp(min-max), the only nontrivial factor
            bool  up  = d > 0.f;
            float nden = up ? den * t + 1.f : den + t;
            float nws  = up ? ws  * t + msg : ws + t * msg;
            m   = up ? msg : m;
            den = nden;
            ws  = nws;
        }
        __syncthreads();
    }
    float agg = (e > s) ? (ws / den) : 0.f;
    g_out[v * D + c] = agg + g_h[v * D + c];
}

// ---------------- output head: out = h @ Wo + bo, one warp per node ----------------
__global__ void k_head(const float* __restrict__ Wo, const float* __restrict__ bo,
                       float* __restrict__ out) {
    int gw   = (blockIdx.x * blockDim.x + threadIdx.x) >> 5;
    int lane = threadIdx.x & 31;
    if (gw >= NN) return;
    float h0 = g_h[gw * D + lane];
    float h1 = g_h[gw * D + lane + 32];
    float h2 = g_h[gw * D + lane + 64];
    float h3 = g_h[gw * D + lane + 96];
#pragma unroll
    for (int o = 0; o < 3; o++) {
        float acc = h0 * __ldg(&Wo[lane * 3 + o]) + h1 * __ldg(&Wo[(lane + 32) * 3 + o]) +
                    h2 * __ldg(&Wo[(lane + 64) * 3 + o]) + h3 * __ldg(&Wo[(lane + 96) * 3 + o]);
#pragma unroll
        for (int off = 16; off; off >>= 1) acc += __shfl_down_sync(0xffffffff, acc, off);
        if (lane == 0) out[gw * 3 + o] = acc + bo[o];
    }
}

// ---------------- launch (first k_gemm_tc kept at launch idx 3 = profiled slot) ----
extern "C" void kernel_launch(void* const* d_in, const int* in_sizes, int n_in,
                              void* d_out, int out_size) {
    const float* x    = (const float*)d_in[0];
    const int*   ei   = (const int*)d_in[1];   // [2, NE]
    const float* attr = (const float*)d_in[2];
    const float* Wn1  = (const float*)d_in[3];
    const float* bn1  = (const float*)d_in[4];
    const float* Wn2  = (const float*)d_in[5];
    const float* bn2  = (const float*)d_in[6];
    const float* We   = (const float*)d_in[7];
    const float* be   = (const float*)d_in[8];
    const float* Wg   = (const float*)d_in[9];  // [4,128,128]
    const float* bg   = (const float*)d_in[10]; // [4,128]
    const float* Wo   = (const float*)d_in[11];
    const float* bo   = (const float*)d_in[12];
    float* out = (float*)d_out;

    const int* src = ei;
    const int* dst = ei + NE;

    float* p_h;
    float* p_out;
    float* p_Wh;
    float* p_Wl;
    cudaGetSymbolAddress((void**)&p_h, g_h);
    cudaGetSymbolAddress((void**)&p_out, g_out);
    cudaGetSymbolAddress((void**)&p_Wh, g_Wh);
    cudaGetSymbolAddress((void**)&p_Wl, g_Wl);

    int gblocks = (NN + TM - 1) / TM;

    // idx 0: encoder stage 1 (independent of CSR)
    k_enc1<<<NN, D>>>(x, Wn1, bn1);                    // g_out = relu(x@Wn1+bn1)
    // idx 1: CSR zero
    k_zero<<<(NN + 255) / 256, 256>>>();
    // idx 2: weight preconversion (needed before idx 3)
    k_prepW<<<((NL + 1) * D * D + 255) / 256, 256>>>(Wn2, Wg);
    // idx 3: encoder GEMM  <-- profiled slot
    k_gemm_tc<<<gblocks, 256>>>(p_out, p_Wh, p_Wl, bn2, p_h);  // g_h = g_out@Wn2+bn2
    // idx 4-7: CSR build finish
    k_hist<<<(NE + 255) / 256, 256>>>(dst);
    k_scan<<<1, 1024>>>();
    k_scatter<<<(NE + 255) / 256, 256>>>(src, dst, attr);
    k_sort<<<(NN + 255) / 256, 256>>>();

    // ---- 4 GENConv layers ----
    for (int l = 0; l < NL; l++) {
        k_agg<<<NN, D>>>(We, be);  // g_out = agg + g_h
        k_gemm_tc<<<gblocks, 256>>>(p_out, p_Wh + (l + 1) * D * D, p_Wl + (l + 1) * D * D,
                                    bg + l * D, p_h);
    }

    // ---- head ----
    k_head<<<(NN * 32 + 255) / 256, 256>>>(Wo, bo, out);
}

// round 9
// speedup vs baseline: 1.3334x; 1.2130x over previous
#include <cuda_runtime.h>
#include <math.h>
#include <stdint.h>

#define D   128
#define NN  30000
#define NE  480000
#define NL  4
#define EPSV 1e-7f

// ---------------- device scratch (static, no allocation) ----------------
__device__ float g_h[NN * D];     // current node features
__device__ float g_out[NN * D];   // post-aggregation (agg + residual)
__device__ int   g_srcs[NE];      // CSR-ordered source node per edge
__device__ float g_attrs[NE];     // CSR-ordered edge attr scalar per edge
__device__ int   g_eids[NE];      // CSR-ordered original edge ids (determinism sort key)
__device__ int   g_row[NN + 1];   // CSR row offsets
__device__ int   g_cur[NN];       // histogram / scatter cursor
// preconverted tf32 hi/lo weights: slot 0 = Wn2, slots 1..4 = Wg[0..3]
__device__ float g_Wh[(NL + 1) * D * D];
__device__ float g_Wl[(NL + 1) * D * D];
// global max of h per GEMM (order-preserving uint key). Zero-init = -NaN key
// (below all real keys). atomicMax is idempotent across graph replays -> no reset.
__device__ unsigned g_hmaxk[NL + 1];

// order-preserving float<->uint key (monotone: a<b <=> key(a)<key(b))
__device__ __forceinline__ unsigned fkey(float f) {
    unsigned u = __float_as_uint(f);
    return (u & 0x80000000u) ? ~u : (u | 0x80000000u);
}
__device__ __forceinline__ float fdec(unsigned k) {
    return (k & 0x80000000u) ? __uint_as_float(k & 0x7FFFFFFFu) : __uint_as_float(~k);
}
__device__ __forceinline__ float ex2f(float x) {
    float r;
    asm("ex2.approx.ftz.f32 %0, %1;" : "=f"(r) : "f"(x));
    return r;
}

// ---------------- CSR build ----------------
__global__ void k_zero() {
    int i = blockIdx.x * blockDim.x + threadIdx.x;
    if (i < NN) g_cur[i] = 0;
}

__global__ void k_hist(const int* __restrict__ dst) {
    int e = blockIdx.x * blockDim.x + threadIdx.x;
    if (e < NE) atomicAdd(&g_cur[dst[e]], 1);
}

__global__ void k_scan() {
    __shared__ int ssum[1024];
    int t = threadIdx.x;
    const int CH = (NN + 1023) / 1024;  // 30
    int base = t * CH;
    int s = 0;
    for (int i = 0; i < CH; i++) {
        int idx = base + i;
        if (idx < NN) s += g_cur[idx];
    }
    ssum[t] = s;
    __syncthreads();
    for (int off = 1; off < 1024; off <<= 1) {
        int v = (t >= off) ? ssum[t - off] : 0;
        __syncthreads();
        ssum[t] += v;
        __syncthreads();
    }
    int run = (t == 0) ? 0 : ssum[t - 1];
    for (int i = 0; i < CH; i++) {
        int idx = base + i;
        if (idx < NN) {
            int c = g_cur[idx];
            g_row[idx] = run;
            g_cur[idx] = run;
            run += c;
        }
    }
    if (t == 1023) g_row[NN] = run;
}

__global__ void k_scatter(const int* __restrict__ src, const int* __restrict__ dst,
                          const float* __restrict__ attr) {
    int e = blockIdx.x * blockDim.x + threadIdx.x;
    if (e >= NE) return;
    int d = dst[e];
    int pos = atomicAdd(&g_cur[d], 1);
    g_eids[pos]  = e;
    g_srcs[pos]  = src[e];
    g_attrs[pos] = attr[e];
}

__global__ void k_sort() {
    int v = blockIdx.x * blockDim.x + threadIdx.x;
    if (v >= NN) return;
    int s = g_row[v], e = g_row[v + 1];
    for (int i = s + 1; i < e; i++) {
        int   key = g_eids[i];
        int   sr  = g_srcs[i];
        float at  = g_attrs[i];
        int j = i - 1;
        while (j >= s && g_eids[j] > key) {
            g_eids[j + 1]  = g_eids[j];
            g_srcs[j + 1]  = g_srcs[j];
            g_attrs[j + 1] = g_attrs[j];
            j--;
        }
        g_eids[j + 1]  = key;
        g_srcs[j + 1]  = sr;
        g_attrs[j + 1] = at;
    }
}

// ---------------- node encoder stage 1: h1 = relu(x @ Wn1 + bn1) ----------------
__global__ void k_enc1(const float* __restrict__ x, const float* __restrict__ Wn1,
                       const float* __restrict__ bn1) {
    int v = blockIdx.x;
    int c = threadIdx.x;
    __shared__ float sx[7];
    if (c < 7) sx[c] = x[v * 7 + c];
    __syncthreads();
    float acc = bn1[c];
#pragma unroll
    for (int k = 0; k < 7; k++) acc += sx[k] * Wn1[k * D + c];
    g_out[v * D + c] = fmaxf(acc, 0.f);
}

// ---------------- weight preconversion: W -> tf32 hi/lo (once per launch) -------
__device__ __forceinline__ uint32_t f2tf32(float x) {
    uint32_t r;
    asm("cvt.rna.tf32.f32 %0, %1;" : "=r"(r) : "f"(x));
    return r;
}

__global__ void k_prepW(const float* __restrict__ Wn2, const float* __restrict__ Wg) {
    int i = blockIdx.x * blockDim.x + threadIdx.x;  // (NL+1)*D*D = 81920
    if (i >= (NL + 1) * D * D) return;
    int m = i / (D * D);
    int j = i - m * D * D;
    float w = (m == 0) ? Wn2[j] : Wg[(m - 1) * D * D + j];
    float hi = __uint_as_float(f2tf32(w));
    g_Wh[i] = hi;
    g_Wl[i] = __uint_as_float(f2tf32(w - hi));
}

// ---------------- tensor-core 64x128 Linear (3xTF32): C = A @ W + b ----------------
// Epilogue also computes global max of outputs into g_hmaxk[slot] (for k_agg's
// softmax shift bound). Warp shfl-reduce + 1 atomicMax per warp: ~free.
__device__ __forceinline__ void mma_tf32(float* c, const uint32_t* a, const uint32_t* b) {
    asm volatile(
        "mma.sync.aligned.m16n8k8.row.col.f32.tf32.tf32.f32 "
        "{%0,%1,%2,%3}, {%4,%5,%6,%7}, {%8,%9}, {%0,%1,%2,%3};"
        : "+f"(c[0]), "+f"(c[1]), "+f"(c[2]), "+f"(c[3])
        : "r"(a[0]), "r"(a[1]), "r"(a[2]), "r"(a[3]), "r"(b[0]), "r"(b[1]));
}

#define GK 16   // K chunk
#define TM 64   // rows per block

__global__ __launch_bounds__(256, 2) void k_gemm_tc(const float* __restrict__ A,
                                                    const float* __restrict__ Wh,
                                                    const float* __restrict__ Wl,
                                                    const float* __restrict__ b,
                                                    float* __restrict__ C, int slot) {
    __shared__ float sWh[GK][136], sWl[GK][136];
    __shared__ float sAh[TM][20], sAl[TM][20];
    int tid  = threadIdx.x;          // 256
    int w    = tid >> 5;
    int lane = tid & 31;
    int g    = lane >> 2;
    int t4   = lane & 3;
    int rowbase = blockIdx.x * TM;
    int n0 = w * 16;

    float acc[4][2][4];
#pragma unroll
    for (int mt = 0; mt < 4; mt++)
#pragma unroll
        for (int nt = 0; nt < 2; nt++)
#pragma unroll
            for (int i = 0; i < 4; i++) acc[mt][nt][i] = 0.f;

    for (int kc = 0; kc < D; kc += GK) {
#pragma unroll
        for (int i = tid; i < 512; i += 256) {
            int r = i >> 5, c4 = i & 31;
            *(float4*)&sWh[r][c4 * 4] = ((const float4*)(Wh + (kc + r) * D))[c4];
            *(float4*)&sWl[r][c4 * 4] = ((const float4*)(Wl + (kc + r) * D))[c4];
        }
        {
            int i = tid;
            int r = i >> 2, c4 = i & 3;
            int gr = rowbase + r;
            float4 av = (gr < NN) ? ((const float4*)(A + gr * D + kc))[c4]
                                  : make_float4(0.f, 0.f, 0.f, 0.f);
            float4 hi, lo;
            hi.x = __uint_as_float(f2tf32(av.x)); lo.x = __uint_as_float(f2tf32(av.x - hi.x));
            hi.y = __uint_as_float(f2tf32(av.y)); lo.y = __uint_as_float(f2tf32(av.y - hi.y));
            hi.z = __uint_as_float(f2tf32(av.z)); lo.z = __uint_as_float(f2tf32(av.z - hi.z));
            hi.w = __uint_as_float(f2tf32(av.w)); lo.w = __uint_as_float(f2tf32(av.w - hi.w));
            *(float4*)&sAh[r][c4 * 4] = hi;
            *(float4*)&sAl[r][c4 * 4] = lo;
        }
        __syncthreads();

#pragma unroll
        for (int kt = 0; kt < GK / 8; kt++) {
            int k8 = kt * 8;
            uint32_t bh[2][2], bl[2][2];
#pragma unroll
            for (int nt = 0; nt < 2; nt++) {
                int n = n0 + nt * 8 + g;
                bh[nt][0] = __float_as_uint(sWh[k8 + t4][n]);
                bh[nt][1] = __float_as_uint(sWh[k8 + t4 + 4][n]);
                bl[nt][0] = __float_as_uint(sWl[k8 + t4][n]);
                bl[nt][1] = __float_as_uint(sWl[k8 + t4 + 4][n]);
            }
#pragma unroll
            for (int mt = 0; mt < 4; mt++) {
                int r0 = mt * 16 + g;
                uint32_t ah[4], al[4];
                ah[0] = __float_as_uint(sAh[r0][k8 + t4]);
                ah[1] = __float_as_uint(sAh[r0 + 8][k8 + t4]);
                ah[2] = __float_as_uint(sAh[r0][k8 + t4 + 4]);
                ah[3] = __float_as_uint(sAh[r0 + 8][k8 + t4 + 4]);
                al[0] = __float_as_uint(sAl[r0][k8 + t4]);
                al[1] = __float_as_uint(sAl[r0 + 8][k8 + t4]);
                al[2] = __float_as_uint(sAl[r0][k8 + t4 + 4]);
                al[3] = __float_as_uint(sAl[r0 + 8][k8 + t4 + 4]);
#pragma unroll
                for (int nt = 0; nt < 2; nt++) {
                    mma_tf32(acc[mt][nt], al, bh[nt]);  // small terms first
                    mma_tf32(acc[mt][nt], ah, bl[nt]);
                    mma_tf32(acc[mt][nt], ah, bh[nt]);
                }
            }
        }
        __syncthreads();
    }

    float tmax = -1e30f;
#pragma unroll
    for (int mt = 0; mt < 4; mt++) {
#pragma unroll
        for (int nt = 0; nt < 2; nt++) {
            int n = n0 + nt * 8 + t4 * 2;
            float2 bb = *(const float2*)&b[n];
            float2 o0 = make_float2(acc[mt][nt][0] + bb.x, acc[mt][nt][1] + bb.y);
            float2 o1 = make_float2(acc[mt][nt][2] + bb.x, acc[mt][nt][3] + bb.y);
            tmax = fmaxf(tmax, fmaxf(fmaxf(o0.x, o0.y), fmaxf(o1.x, o1.y)));
            int r = rowbase + mt * 16 + g;
            if (r < NN) *(float2*)&C[r * D + n] = o0;
            int r2 = r + 8;
            if (r2 < NN) *(float2*)&C[r2 * D + n] = o1;
        }
    }
#pragma unroll
    for (int off = 16; off; off >>= 1)
        tmax = fmaxf(tmax, __shfl_xor_sync(0xffffffff, tmax, off));
    if (lane == 0) atomicMax(&g_hmaxk[slot], fkey(tmax));
}

// ---------------- GENConv aggregation ----------------
// One block of 64 threads per node, 2 channels per thread (float2).
// Softmax shift uses precomputed per-channel upper bound derived from the
// global h max (g_hmaxk[slot]); shift-invariance makes this exact, and it
// removes the online-softmax compare/select chain (9 vs 15 instr/channel).
//   bound_c = relu(hmax + max(be_c, we_c+be_c)) + eps >= every msg in channel c
//   (attr in [0,1) -> a*we+be bounded by its endpoints; hv <= hmax)
__global__ void k_agg(const float* __restrict__ We, const float* __restrict__ be,
                      int slot) {
    int v  = blockIdx.x;
    int c2 = threadIdx.x;            // 0..63 -> channels 2*c2, 2*c2+1
    __shared__ int   s_src[64];
    __shared__ float s_attr[64];
    int s = g_row[v], e = g_row[v + 1];
    float2 we2 = ((const float2*)We)[c2];
    float2 be2 = ((const float2*)be)[c2];
    const float L2E = 1.4426950408889634f;
    float hmax = fdec(g_hmaxk[slot]);
    float blx = (fmaxf(hmax + fmaxf(be2.x, we2.x + be2.x), 0.f) + EPSV) * L2E;
    float bly = (fmaxf(hmax + fmaxf(be2.y, we2.y + be2.y), 0.f) + EPSV) * L2E;
    float denx = 0.f, wsx = 0.f, deny = 0.f, wsy = 0.f;
    const float2* h2 = (const float2*)g_h;
    for (int base = s; base < e; base += 64) {
        int n = min(64, e - base);
        if (c2 < n) {
            s_src[c2]  = g_srcs[base + c2];
            s_attr[c2] = g_attrs[base + c2];
        }
        __syncthreads();
        for (int i = 0; i < n; i++) {
            float2 hv = h2[s_src[i] * 64 + c2];
            float a = s_attr[i];
            float mx = fmaxf(hv.x + fmaf(a, we2.x, be2.x), 0.f) + EPSV;
            float my = fmaxf(hv.y + fmaf(a, we2.y, be2.y), 0.f) + EPSV;
            float ex = ex2f(fmaf(mx, L2E, -blx));   // exp(mx - bound_x), <= 1
            float ey = ex2f(fmaf(my, L2E, -bly));
            denx += ex; wsx = fmaf(ex, mx, wsx);
            deny += ey; wsy = fmaf(ey, my, wsy);
        }
        __syncthreads();
    }
    float2 hself = h2[v * 64 + c2];
    float2 o;
    o.x = ((e > s) ? (wsx / denx) : 0.f) + hself.x;
    o.y = ((e > s) ? (wsy / deny) : 0.f) + hself.y;
    ((float2*)g_out)[v * 64 + c2] = o;
}

// ---------------- output head: out = h @ Wo + bo, one warp per node ----------------
__global__ void k_head(const float* __restrict__ Wo, const float* __restrict__ bo,
                       float* __restrict__ out) {
    int gw   = (blockIdx.x * blockDim.x + threadIdx.x) >> 5;
    int lane = threadIdx.x & 31;
    if (gw >= NN) return;
    float h0 = g_h[gw * D + lane];
    float h1 = g_h[gw * D + lane + 32];
    float h2 = g_h[gw * D + lane + 64];
    float h3 = g_h[gw * D + lane + 96];
#pragma unroll
    for (int o = 0; o < 3; o++) {
        float acc = h0 * __ldg(&Wo[lane * 3 + o]) + h1 * __ldg(&Wo[(lane + 32) * 3 + o]) +
                    h2 * __ldg(&Wo[(lane + 64) * 3 + o]) + h3 * __ldg(&Wo[(lane + 96) * 3 + o]);
#pragma unroll
        for (int off = 16; off; off >>= 1) acc += __shfl_down_sync(0xffffffff, acc, off);
        if (lane == 0) out[gw * 3 + o] = acc + bo[o];
    }
}

// ---------------- launch (first k_gemm_tc kept at launch idx 3 = profiled slot) ----
extern "C" void kernel_launch(void* const* d_in, const int* in_sizes, int n_in,
                              void* d_out, int out_size) {
    const float* x    = (const float*)d_in[0];
    const int*   ei   = (const int*)d_in[1];   // [2, NE]
    const float* attr = (const float*)d_in[2];
    const float* Wn1  = (const float*)d_in[3];
    const float* bn1  = (const float*)d_in[4];
    const float* Wn2  = (const float*)d_in[5];
    const float* bn2  = (const float*)d_in[6];
    const float* We   = (const float*)d_in[7];
    const float* be   = (const float*)d_in[8];
    const float* Wg   = (const float*)d_in[9];  // [4,128,128]
    const float* bg   = (const float*)d_in[10]; // [4,128]
    const float* Wo   = (const float*)d_in[11];
    const float* bo   = (const float*)d_in[12];
    float* out = (float*)d_out;

    const int* src = ei;
    const int* dst = ei + NE;

    float* p_h;
    float* p_out;
    float* p_Wh;
    float* p_Wl;
    cudaGetSymbolAddress((void**)&p_h, g_h);
    cudaGetSymbolAddress((void**)&p_out, g_out);
    cudaGetSymbolAddress((void**)&p_Wh, g_Wh);
    cudaGetSymbolAddress((void**)&p_Wl, g_Wl);

    int gblocks = (NN + TM - 1) / TM;

    // idx 0: encoder stage 1 (independent of CSR)
    k_enc1<<<NN, D>>>(x, Wn1, bn1);                    // g_out = relu(x@Wn1+bn1)
    // idx 1: CSR zero
    k_zero<<<(NN + 255) / 256, 256>>>();
    // idx 2: weight preconversion (needed before idx 3)
    k_prepW<<<((NL + 1) * D * D + 255) / 256, 256>>>(Wn2, Wg);
    // idx 3: encoder GEMM  <-- profiled slot
    k_gemm_tc<<<gblocks, 256>>>(p_out, p_Wh, p_Wl, bn2, p_h, 0);
    // idx 4-7: CSR build finish
    k_hist<<<(NE + 255) / 256, 256>>>(dst);
    k_scan<<<1, 1024>>>();
    k_scatter<<<(NE + 255) / 256, 256>>>(src, dst, attr);
    k_sort<<<(NN + 255) / 256, 256>>>();

    // ---- 4 GENConv layers ----
    for (int l = 0; l < NL; l++) {
        k_agg<<<NN, 64>>>(We, be, l);  // g_out = agg + g_h, bound from slot l
        k_gemm_tc<<<gblocks, 256>>>(p_out, p_Wh + (l + 1) * D * D, p_Wl + (l + 1) * D * D,
                                    bg + l * D, p_h, l + 1);
    }

    // ---- head ----
    k_head<<<(NN * 32 + 255) / 256, 256>>>(Wo, bo, out);
}

// round 10
// speedup vs baseline: 1.4549x; 1.0911x over previous
#include <cuda_runtime.h>
#include <cuda_bf16.h>
#include <math.h>
#include <stdint.h>

#define D   128
#define NN  30000
#define NE  480000
#define NL  4
#define EPSV 1e-7f

// ---------------- device scratch (static, no allocation) ----------------
__device__ float g_h[NN * D];     // current node features
__device__ float g_out[NN * D];   // post-aggregation (agg + residual)
__device__ int   g_srcs[NE];      // CSR-ordered source node per edge
__device__ float g_attrs[NE];     // CSR-ordered edge attr scalar per edge
__device__ int   g_eids[NE];      // CSR-ordered original edge ids (determinism sort key)
__device__ int   g_row[NN + 1];   // CSR row offsets
__device__ int   g_cur[NN];       // histogram / scatter cursor
// preconverted packed TRANSPOSED bf16 hi/lo weights: [m][n][k/2] uint32 (2 bf16, k-pair)
// slot 0 = Wn2, slots 1..4 = Wg[0..3]
__device__ uint32_t g_Wph[(NL + 1) * D * D / 2];
__device__ uint32_t g_Wpl[(NL + 1) * D * D / 2];
// global max of h per GEMM (order-preserving uint key). Zero-init key decodes below
// all real values; atomicMax is idempotent across graph replays -> no reset needed.
__device__ unsigned g_hmaxk[NL + 1];

// order-preserving float<->uint key (monotone: a<b <=> key(a)<key(b))
__device__ __forceinline__ unsigned fkey(float f) {
    unsigned u = __float_as_uint(f);
    return (u & 0x80000000u) ? ~u : (u | 0x80000000u);
}
__device__ __forceinline__ float fdec(unsigned k) {
    return (k & 0x80000000u) ? __uint_as_float(k & 0x7FFFFFFFu) : __uint_as_float(~k);
}
__device__ __forceinline__ float ex2f(float x) {
    float r;
    asm("ex2.approx.ftz.f32 %0, %1;" : "=f"(r) : "f"(x));
    return r;
}
__device__ __forceinline__ uint32_t packbf2(float lo, float hi) {
    __nv_bfloat162 t = __floats2bfloat162_rn(lo, hi);
    return *(uint32_t*)&t;
}

// ---------------- CSR build ----------------
__global__ void k_zero() {
    int i = blockIdx.x * blockDim.x + threadIdx.x;
    if (i < NN) g_cur[i] = 0;
}

__global__ void k_hist(const int* __restrict__ dst) {
    int e = blockIdx.x * blockDim.x + threadIdx.x;
    if (e < NE) atomicAdd(&g_cur[dst[e]], 1);
}

__global__ void k_scan() {
    __shared__ int ssum[1024];
    int t = threadIdx.x;
    const int CH = (NN + 1023) / 1024;  // 30
    int base = t * CH;
    int s = 0;
    for (int i = 0; i < CH; i++) {
        int idx = base + i;
        if (idx < NN) s += g_cur[idx];
    }
    ssum[t] = s;
    __syncthreads();
    for (int off = 1; off < 1024; off <<= 1) {
        int v = (t >= off) ? ssum[t - off] : 0;
        __syncthreads();
        ssum[t] += v;
        __syncthreads();
    }
    int run = (t == 0) ? 0 : ssum[t - 1];
    for (int i = 0; i < CH; i++) {
        int idx = base + i;
        if (idx < NN) {
            int c = g_cur[idx];
            g_row[idx] = run;
            g_cur[idx] = run;
            run += c;
        }
    }
    if (t == 1023) g_row[NN] = run;
}

__global__ void k_scatter(const int* __restrict__ src, const int* __restrict__ dst,
                          const float* __restrict__ attr) {
    int e = blockIdx.x * blockDim.x + threadIdx.x;
    if (e >= NE) return;
    int d = dst[e];
    int pos = atomicAdd(&g_cur[d], 1);
    g_eids[pos]  = e;
    g_srcs[pos]  = src[e];
    g_attrs[pos] = attr[e];
}

__global__ void k_sort() {
    int v = blockIdx.x * blockDim.x + threadIdx.x;
    if (v >= NN) return;
    int s = g_row[v], e = g_row[v + 1];
    for (int i = s + 1; i < e; i++) {
        int   key = g_eids[i];
        int   sr  = g_srcs[i];
        float at  = g_attrs[i];
        int j = i - 1;
        while (j >= s && g_eids[j] > key) {
            g_eids[j + 1]  = g_eids[j];
            g_srcs[j + 1]  = g_srcs[j];
            g_attrs[j + 1] = g_attrs[j];
            j--;
        }
        g_eids[j + 1]  = key;
        g_srcs[j + 1]  = sr;
        g_attrs[j + 1] = at;
    }
}

// ---------------- node encoder stage 1: h1 = relu(x @ Wn1 + bn1) ----------------
__global__ void k_enc1(const float* __restrict__ x, const float* __restrict__ Wn1,
                       const float* __restrict__ bn1) {
    int v = blockIdx.x;
    int c = threadIdx.x;
    __shared__ float sx[7];
    if (c < 7) sx[c] = x[v * 7 + c];
    __syncthreads();
    float acc = bn1[c];
#pragma unroll
    for (int k = 0; k < 7; k++) acc += sx[k] * Wn1[k * D + c];
    g_out[v * D + c] = fmaxf(acc, 0.f);
}

// ---------------- weight preconversion: W -> packed transposed bf16 hi/lo --------
// g_Wph[m][n][kk] packs bf16(W_m[2kk][n]), bf16(W_m[2kk+1][n]); g_Wpl the residuals.
__global__ void k_prepW(const float* __restrict__ Wn2, const float* __restrict__ Wg) {
    int i = blockIdx.x * blockDim.x + threadIdx.x;  // (NL+1)*D*D/2 = 40960
    if (i >= (NL + 1) * D * D / 2) return;
    int m   = i >> 13;        // 8192 packed per matrix
    int rem = i & 8191;
    int n   = rem >> 6;
    int kk  = rem & 63;
    const float* W = (m == 0) ? Wn2 : (Wg + (m - 1) * D * D);
    float w0 = W[(2 * kk) * D + n];
    float w1 = W[(2 * kk + 1) * D + n];
    __nv_bfloat16 h0 = __float2bfloat16(w0);
    __nv_bfloat16 h1 = __float2bfloat16(w1);
    g_Wph[i] = packbf2(__bfloat162float(h0), __bfloat162float(h1));
    g_Wpl[i] = packbf2(w0 - __bfloat162float(h0), w1 - __bfloat162float(h1));
}

// ---------------- tensor-core 64x128 Linear (2-term bf16, m16n8k16) --------------
// C = A @ W + b. Each 32-bit fragment reg carries 2 bf16 k-values: halves the
// fragment LDS traffic and the MMA count vs R9's tf32 m16n8k8 (L1 was 50.6%).
// Stride-12 smem rows make (12g + t4) mod 32 a 32-lane permutation -> no conflicts.
// Epilogue also reduces global max of outputs into g_hmaxk[slot] for k_agg.
__device__ __forceinline__ void mma_bf16(float* c, const uint32_t* a, const uint32_t* b) {
    asm volatile(
        "mma.sync.aligned.m16n8k16.row.col.f32.bf16.bf16.f32 "
        "{%0,%1,%2,%3}, {%4,%5,%6,%7}, {%8,%9}, {%0,%1,%2,%3};"
        : "+f"(c[0]), "+f"(c[1]), "+f"(c[2]), "+f"(c[3])
        : "r"(a[0]), "r"(a[1]), "r"(a[2]), "r"(a[3]), "r"(b[0]), "r"(b[1]));
}

#define TM 64   // rows per block

__global__ __launch_bounds__(256, 2) void k_gemm_bf(const float* __restrict__ A,
                                                    const uint32_t* __restrict__ Wph,
                                                    const uint32_t* __restrict__ Wpl,
                                                    const float* __restrict__ b,
                                                    float* __restrict__ C, int slot) {
    __shared__ uint32_t sBh[D][12], sBl[D][12];   // [n][packed k-chunk], cols 0..7 used
    __shared__ uint32_t sAh[TM][12], sAl[TM][12]; // [row][packed k-chunk]
    int tid  = threadIdx.x;          // 256
    int w    = tid >> 5;             // warp 0..7: n-slice [w*16, w*16+16)
    int lane = tid & 31;
    int g    = lane >> 2;            // 0..7
    int t4   = lane & 3;             // 0..3
    int rowbase = blockIdx.x * TM;
    int n0 = w * 16;

    float acc[4][2][4];
#pragma unroll
    for (int mt = 0; mt < 4; mt++)
#pragma unroll
        for (int nt = 0; nt < 2; nt++)
#pragma unroll
            for (int i = 0; i < 4; i++) acc[mt][nt][i] = 0.f;

    for (int kc = 0; kc < D / 16; kc++) {   // 8 chunks of k16
        // stage W chunk: per n, 8 packed uint32 -> 2 uint4 per row; 1 uint4/thread
        {
            int n = tid >> 1, half = tid & 1;
            const uint4* ph = (const uint4*)&Wph[n * 64 + kc * 8 + half * 4];
            const uint4* pl = (const uint4*)&Wpl[n * 64 + kc * 8 + half * 4];
            *(uint4*)&sBh[n][half * 4] = *ph;
            *(uint4*)&sBl[n][half * 4] = *pl;
        }
        // stage A chunk: load fp32 float4, split bf16 hi/lo, store packed uint2
        {
            int r = tid >> 2, c4 = tid & 3;
            int gr = rowbase + r;
            float4 av = (gr < NN) ? ((const float4*)(A + gr * D + kc * 16))[c4]
                                  : make_float4(0.f, 0.f, 0.f, 0.f);
            __nv_bfloat16 hx = __float2bfloat16(av.x), hy = __float2bfloat16(av.y);
            __nv_bfloat16 hz = __float2bfloat16(av.z), hw = __float2bfloat16(av.w);
            uint2 hp = make_uint2(packbf2(__bfloat162float(hx), __bfloat162float(hy)),
                                  packbf2(__bfloat162float(hz), __bfloat162float(hw)));
            uint2 lp = make_uint2(packbf2(av.x - __bfloat162float(hx),
                                          av.y - __bfloat162float(hy)),
                                  packbf2(av.z - __bfloat162float(hz),
                                          av.w - __bfloat162float(hw)));
            *(uint2*)&sAh[r][c4 * 2] = hp;
            *(uint2*)&sAl[r][c4 * 2] = lp;
        }
        __syncthreads();

        // one m16n8k16 step covers the whole 16-k chunk
        uint32_t bh[2][2], bl[2][2];
#pragma unroll
        for (int nt = 0; nt < 2; nt++) {
            int n = n0 + nt * 8 + g;
            bh[nt][0] = sBh[n][t4];
            bh[nt][1] = sBh[n][t4 + 4];
            bl[nt][0] = sBl[n][t4];
            bl[nt][1] = sBl[n][t4 + 4];
        }
#pragma unroll
        for (int mt = 0; mt < 4; mt++) {
            int r0 = mt * 16 + g;
            uint32_t ah[4], al[4];
            ah[0] = sAh[r0][t4];
            ah[1] = sAh[r0 + 8][t4];
            ah[2] = sAh[r0][t4 + 4];
            ah[3] = sAh[r0 + 8][t4 + 4];
            al[0] = sAl[r0][t4];
            al[1] = sAl[r0 + 8][t4];
            al[2] = sAl[r0][t4 + 4];
            al[3] = sAl[r0 + 8][t4 + 4];
#pragma unroll
            for (int nt = 0; nt < 2; nt++) {
                mma_bf16(acc[mt][nt], al, bh[nt]);  // small terms first
                mma_bf16(acc[mt][nt], ah, bl[nt]);
                mma_bf16(acc[mt][nt], ah, bh[nt]);
            }
        }
        __syncthreads();
    }

    float tmax = -1e30f;
#pragma unroll
    for (int mt = 0; mt < 4; mt++) {
#pragma unroll
        for (int nt = 0; nt < 2; nt++) {
            int n = n0 + nt * 8 + t4 * 2;
            float2 bb = *(const float2*)&b[n];
            float2 o0 = make_float2(acc[mt][nt][0] + bb.x, acc[mt][nt][1] + bb.y);
            float2 o1 = make_float2(acc[mt][nt][2] + bb.x, acc[mt][nt][3] + bb.y);
            tmax = fmaxf(tmax, fmaxf(fmaxf(o0.x, o0.y), fmaxf(o1.x, o1.y)));
            int r = rowbase + mt * 16 + g;
            if (r < NN) *(float2*)&C[r * D + n] = o0;
            int r2 = r + 8;
            if (r2 < NN) *(float2*)&C[r2 * D + n] = o1;
        }
    }
#pragma unroll
    for (int off = 16; off; off >>= 1)
        tmax = fmaxf(tmax, __shfl_xor_sync(0xffffffff, tmax, off));
    if (lane == 0) atomicMax(&g_hmaxk[slot], fkey(tmax));
}

// ---------------- GENConv aggregation (R9 version — proven) ----------------
// 64 threads per node, 2 channels/thread; softmax shift via precomputed global
// upper bound (shift-invariance makes this exact; no compare/select chain).
__global__ void k_agg(const float* __restrict__ We, const float* __restrict__ be,
                      int slot) {
    int v  = blockIdx.x;
    int c2 = threadIdx.x;            // 0..63 -> channels 2*c2, 2*c2+1
    __shared__ int   s_src[64];
    __shared__ float s_attr[64];
    int s = g_row[v], e = g_row[v + 1];
    float2 we2 = ((const float2*)We)[c2];
    float2 be2 = ((const float2*)be)[c2];
    const float L2E = 1.4426950408889634f;
    float hmax = fdec(g_hmaxk[slot]);
    float blx = (fmaxf(hmax + fmaxf(be2.x, we2.x + be2.x), 0.f) + EPSV) * L2E;
    float bly = (fmaxf(hmax + fmaxf(be2.y, we2.y + be2.y), 0.f) + EPSV) * L2E;
    float denx = 0.f, wsx = 0.f, deny = 0.f, wsy = 0.f;
    const float2* h2 = (const float2*)g_h;
    for (int base = s; base < e; base += 64) {
        int n = min(64, e - base);
        if (c2 < n) {
            s_src[c2]  = g_srcs[base + c2];
            s_attr[c2] = g_attrs[base + c2];
        }
        __syncthreads();
        for (int i = 0; i < n; i++) {
            float2 hv = h2[s_src[i] * 64 + c2];
            float a = s_attr[i];
            float mx = fmaxf(hv.x + fmaf(a, we2.x, be2.x), 0.f) + EPSV;
            float my = fmaxf(hv.y + fmaf(a, we2.y, be2.y), 0.f) + EPSV;
            float ex = ex2f(fmaf(mx, L2E, -blx));   // exp(mx - bound_x), <= 1
            float ey = ex2f(fmaf(my, L2E, -bly));
            denx += ex; wsx = fmaf(ex, mx, wsx);
            deny += ey; wsy = fmaf(ey, my, wsy);
        }
        __syncthreads();
    }
    float2 hself = h2[v * 64 + c2];
    float2 o;
    o.x = ((e > s) ? (wsx / denx) : 0.f) + hself.x;
    o.y = ((e > s) ? (wsy / deny) : 0.f) + hself.y;
    ((float2*)g_out)[v * 64 + c2] = o;
}

// ---------------- output head: out = h @ Wo + bo, one warp per node ----------------
__global__ void k_head(const float* __restrict__ Wo, const float* __restrict__ bo,
                       float* __restrict__ out) {
    int gw   = (blockIdx.x * blockDim.x + threadIdx.x) >> 5;
    int lane = threadIdx.x & 31;
    if (gw >= NN) return;
    float h0 = g_h[gw * D + lane];
    float h1 = g_h[gw * D + lane + 32];
    float h2 = g_h[gw * D + lane + 64];
    float h3 = g_h[gw * D + lane + 96];
#pragma unroll
    for (int o = 0; o < 3; o++) {
        float acc = h0 * __ldg(&Wo[lane * 3 + o]) + h1 * __ldg(&Wo[(lane + 32) * 3 + o]) +
                    h2 * __ldg(&Wo[(lane + 64) * 3 + o]) + h3 * __ldg(&Wo[(lane + 96) * 3 + o]);
#pragma unroll
        for (int off = 16; off; off >>= 1) acc += __shfl_down_sync(0xffffffff, acc, off);
        if (lane == 0) out[gw * 3 + o] = acc + bo[o];
    }
}

// ---------------- launch (first GEMM kept at launch idx 3 = profiled slot) ----------
extern "C" void kernel_launch(void* const* d_in, const int* in_sizes, int n_in,
                              void* d_out, int out_size) {
    const float* x    = (const float*)d_in[0];
    const int*   ei   = (const int*)d_in[1];   // [2, NE]
    const float* attr = (const float*)d_in[2];
    const float* Wn1  = (const float*)d_in[3];
    const float* bn1  = (const float*)d_in[4];
    const float* Wn2  = (const float*)d_in[5];
    const float* bn2  = (const float*)d_in[6];
    const float* We   = (const float*)d_in[7];
    const float* be   = (const float*)d_in[8];
    const float* Wg   = (const float*)d_in[9];  // [4,128,128]
    const float* bg   = (const float*)d_in[10]; // [4,128]
    const float* Wo   = (const float*)d_in[11];
    const float* bo   = (const float*)d_in[12];
    float* out = (float*)d_out;

    const int* src = ei;
    const int* dst = ei + NE;

    float* p_h;
    float* p_out;
    uint32_t* p_Wph;
    uint32_t* p_Wpl;
    cudaGetSymbolAddress((void**)&p_h, g_h);
    cudaGetSymbolAddress((void**)&p_out, g_out);
    cudaGetSymbolAddress((void**)&p_Wph, g_Wph);
    cudaGetSymbolAddress((void**)&p_Wpl, g_Wpl);

    int gblocks = (NN + TM - 1) / TM;

    // idx 0: encoder stage 1 (independent of CSR)
    k_enc1<<<NN, D>>>(x, Wn1, bn1);                    // g_out = relu(x@Wn1+bn1)
    // idx 1: CSR zero
    k_zero<<<(NN + 255) / 256, 256>>>();
    // idx 2: weight preconversion (needed before idx 3)
    k_prepW<<<((NL + 1) * D * D / 2 + 255) / 256, 256>>>(Wn2, Wg);
    // idx 3: encoder GEMM  <-- profiled slot
    k_gemm_bf<<<gblocks, 256>>>(p_out, p_Wph, p_Wpl, bn2, p_h, 0);
    // idx 4-7: CSR build finish
    k_hist<<<(NE + 255) / 256, 256>>>(dst);
    k_scan<<<1, 1024>>>();
    k_scatter<<<(NE + 255) / 256, 256>>>(src, dst, attr);
    k_sort<<<(NN + 255) / 256, 256>>>();

    // ---- 4 GENConv layers ----
    for (int l = 0; l < NL; l++) {
        k_agg<<<NN, 64>>>(We, be, l);  // g_out = agg + g_h, bound from slot l
        k_gemm_bf<<<gblocks, 256>>>(p_out, p_Wph + (l + 1) * D * D / 2,
                                    p_Wpl + (l + 1) * D * D / 2, bg + l * D, p_h, l + 1);
    }

    // ---- head ----
    k_head<<<(NN * 32 + 255) / 256, 256>>>(Wo, bo, out);
}

// round 11
// speedup vs baseline: 1.5766x; 1.0836x over previous
#include <cuda_runtime.h>
#include <cuda_bf16.h>
#include <math.h>
#include <stdint.h>

#define D   128
#define NN  30000
#define NE  480000
#define NL  4
#define EPSV 1e-7f

// ---------------- device scratch (static, no allocation) ----------------
__device__ float g_h[NN * D];     // current node features
__device__ float g_out[NN * D];   // post-aggregation (agg + residual)
__device__ int   g_srcs[NE];      // CSR-ordered source node per edge
__device__ float g_attrs[NE];     // CSR-ordered edge attr scalar per edge
__device__ int   g_eids[NE];      // CSR-ordered original edge ids (determinism sort key)
__device__ int   g_row[NN + 1];   // CSR row offsets
__device__ int   g_cur[NN];       // histogram / scatter cursor
// preconverted packed TRANSPOSED bf16 hi/lo weights: [m][n][k/2] uint32 (2 bf16, k-pair)
// slot 0 = Wn2, slots 1..4 = Wg[0..3]
__device__ uint32_t g_Wph[(NL + 1) * D * D / 2];
__device__ uint32_t g_Wpl[(NL + 1) * D * D / 2];
// global max of h per GEMM (order-preserving uint key). Zero-init key decodes below
// all real values; atomicMax is idempotent across graph replays -> no reset needed.
__device__ unsigned g_hmaxk[NL + 1];

// order-preserving float<->uint key (monotone: a<b <=> key(a)<key(b))
__device__ __forceinline__ unsigned fkey(float f) {
    unsigned u = __float_as_uint(f);
    return (u & 0x80000000u) ? ~u : (u | 0x80000000u);
}
__device__ __forceinline__ float fdec(unsigned k) {
    return (k & 0x80000000u) ? __uint_as_float(k & 0x7FFFFFFFu) : __uint_as_float(~k);
}
__device__ __forceinline__ float ex2f(float x) {
    float r;
    asm("ex2.approx.ftz.f32 %0, %1;" : "=f"(r) : "f"(x));
    return r;
}
__device__ __forceinline__ uint32_t packbf2(float lo, float hi) {
    __nv_bfloat162 t = __floats2bfloat162_rn(lo, hi);
    return *(uint32_t*)&t;
}

// ---------------- CSR build ----------------
__global__ void k_zero() {
    int i = blockIdx.x * blockDim.x + threadIdx.x;
    if (i < NN) g_cur[i] = 0;
}

__global__ void k_hist(const int* __restrict__ dst) {
    int e = blockIdx.x * blockDim.x + threadIdx.x;
    if (e < NE) atomicAdd(&g_cur[dst[e]], 1);
}

__global__ void k_scan() {
    __shared__ int ssum[1024];
    int t = threadIdx.x;
    const int CH = (NN + 1023) / 1024;  // 30
    int base = t * CH;
    int s = 0;
    for (int i = 0; i < CH; i++) {
        int idx = base + i;
        if (idx < NN) s += g_cur[idx];
    }
    ssum[t] = s;
    __syncthreads();
    for (int off = 1; off < 1024; off <<= 1) {
        int v = (t >= off) ? ssum[t - off] : 0;
        __syncthreads();
        ssum[t] += v;
        __syncthreads();
    }
    int run = (t == 0) ? 0 : ssum[t - 1];
    for (int i = 0; i < CH; i++) {
        int idx = base + i;
        if (idx < NN) {
            int c = g_cur[idx];
            g_row[idx] = run;
            g_cur[idx] = run;
            run += c;
        }
    }
    if (t == 1023) g_row[NN] = run;
}

// scatter ONLY edge ids (payloads gathered after sort by k_fill)
__global__ void k_scatter(const int* __restrict__ dst) {
    int e = blockIdx.x * blockDim.x + threadIdx.x;
    if (e >= NE) return;
    int d = dst[e];
    int pos = atomicAdd(&g_cur[d], 1);
    g_eids[pos] = e;
}

// per-node insertion sort of eids only -> deterministic reduction order
__global__ void k_sort() {
    int v = blockIdx.x * blockDim.x + threadIdx.x;
    if (v >= NN) return;
    int s = g_row[v], e = g_row[v + 1];
    for (int i = s + 1; i < e; i++) {
        int key = g_eids[i];
        int j = i - 1;
        while (j >= s && g_eids[j] > key) {
            g_eids[j + 1] = g_eids[j];
            j--;
        }
        g_eids[j + 1] = key;
    }
}

// gather payloads into CSR order
__global__ void k_fill(const int* __restrict__ src, const float* __restrict__ attr) {
    int p = blockIdx.x * blockDim.x + threadIdx.x;
    if (p >= NE) return;
    int e = g_eids[p];
    g_srcs[p]  = src[e];
    g_attrs[p] = attr[e];
}

// ---------------- node encoder stage 1: h1 = relu(x @ Wn1 + bn1) ----------------
__global__ void k_enc1(const float* __restrict__ x, const float* __restrict__ Wn1,
                       const float* __restrict__ bn1) {
    int v = blockIdx.x;
    int c = threadIdx.x;
    __shared__ float sx[7];
    if (c < 7) sx[c] = x[v * 7 + c];
    __syncthreads();
    float acc = bn1[c];
#pragma unroll
    for (int k = 0; k < 7; k++) acc += sx[k] * Wn1[k * D + c];
    g_out[v * D + c] = fmaxf(acc, 0.f);
}

// ---------------- weight preconversion: W -> packed transposed bf16 hi/lo --------
__global__ void k_prepW(const float* __restrict__ Wn2, const float* __restrict__ Wg) {
    int i = blockIdx.x * blockDim.x + threadIdx.x;  // (NL+1)*D*D/2 = 40960
    if (i >= (NL + 1) * D * D / 2) return;
    int m   = i >> 13;
    int rem = i & 8191;
    int n   = rem >> 6;
    int kk  = rem & 63;
    const float* W = (m == 0) ? Wn2 : (Wg + (m - 1) * D * D);
    float w0 = W[(2 * kk) * D + n];
    float w1 = W[(2 * kk + 1) * D + n];
    __nv_bfloat16 h0 = __float2bfloat16(w0);
    __nv_bfloat16 h1 = __float2bfloat16(w1);
    g_Wph[i] = packbf2(__bfloat162float(h0), __bfloat162float(h1));
    g_Wpl[i] = packbf2(w0 - __bfloat162float(h0), w1 - __bfloat162float(h1));
}

// ---------------- tensor-core 64x128 Linear (2-term bf16 + ldmatrix) -------------
// Fragment loads via ldmatrix: A uses m8n8.x4 (four 8x8 sub-tiles = exactly the
// m16n8k16 A fragment), B uses m8n8.x2. 40 scalar LDS/warp/chunk -> 12 LDSM
// (R10 showed L1=48% on fragment LDS). Stride-12 rows: 8-row ldmatrix address
// sets hit banks {0,3,6,1,4,7,2,5} -> conflict-free. Addresses k-invariant.
__device__ __forceinline__ void mma_bf16(float* c, const uint32_t* a, const uint32_t* b) {
    asm volatile(
        "mma.sync.aligned.m16n8k16.row.col.f32.bf16.bf16.f32 "
        "{%0,%1,%2,%3}, {%4,%5,%6,%7}, {%8,%9}, {%0,%1,%2,%3};"
        : "+f"(c[0]), "+f"(c[1]), "+f"(c[2]), "+f"(c[3])
        : "r"(a[0]), "r"(a[1]), "r"(a[2]), "r"(a[3]), "r"(b[0]), "r"(b[1]));
}
__device__ __forceinline__ void ldsm_x4(uint32_t* r, uint32_t addr) {
    asm volatile("ldmatrix.sync.aligned.m8n8.x4.shared.b16 {%0,%1,%2,%3}, [%4];"
                 : "=r"(r[0]), "=r"(r[1]), "=r"(r[2]), "=r"(r[3]) : "r"(addr));
}
__device__ __forceinline__ void ldsm_x2(uint32_t* r, uint32_t addr) {
    asm volatile("ldmatrix.sync.aligned.m8n8.x2.shared.b16 {%0,%1}, [%2];"
                 : "=r"(r[0]), "=r"(r[1]) : "r"(addr));
}

#define TM 64   // rows per block

__global__ __launch_bounds__(256, 2) void k_gemm_bf(const float* __restrict__ A,
                                                    const uint32_t* __restrict__ Wph,
                                                    const uint32_t* __restrict__ Wpl,
                                                    const float* __restrict__ b,
                                                    float* __restrict__ C, int slot) {
    __shared__ uint32_t sBh[D][12], sBl[D][12];   // [n][packed k-chunk], cols 0..7 used
    __shared__ uint32_t sAh[TM][12], sAl[TM][12]; // [row][packed k-chunk]
    int tid  = threadIdx.x;          // 256
    int w    = tid >> 5;             // warp 0..7: n-slice [w*16, w*16+16)
    int lane = tid & 31;
    int g    = lane >> 2;            // 0..7
    int t4   = lane & 3;             // 0..3
    int rowbase = blockIdx.x * TM;
    int n0 = w * 16;

    // ldmatrix lane-address setup (constant across k-chunks; smem buffers reused)
    int lr    = lane & 7;
    int lhalf = (lane >> 3) & 1;
    int lcol  = (lane >> 4) * 4;     // A: k-half select (matrices 2,3 at +16B)
    uint32_t aAh[4], aAl[4], aBh[2], aBl[2];
#pragma unroll
    for (int mt = 0; mt < 4; mt++) {
        int r = mt * 16 + lhalf * 8 + lr;
        aAh[mt] = (uint32_t)__cvta_generic_to_shared(&sAh[r][lcol]);
        aAl[mt] = (uint32_t)__cvta_generic_to_shared(&sAl[r][lcol]);
    }
#pragma unroll
    for (int nt = 0; nt < 2; nt++) {
        int r = n0 + nt * 8 + lr;    // x2: lanes 0-7 -> matrix0 (k0-7), 8-15 -> matrix1
        aBh[nt] = (uint32_t)__cvta_generic_to_shared(&sBh[r][lhalf * 4]);
        aBl[nt] = (uint32_t)__cvta_generic_to_shared(&sBl[r][lhalf * 4]);
    }

    float acc[4][2][4];
#pragma unroll
    for (int mt = 0; mt < 4; mt++)
#pragma unroll
        for (int nt = 0; nt < 2; nt++)
#pragma unroll
            for (int i = 0; i < 4; i++) acc[mt][nt][i] = 0.f;

    for (int kc = 0; kc < D / 16; kc++) {   // 8 chunks of k16
        // stage W chunk: per n, 8 packed uint32 -> 2 uint4; 1 uint4/thread
        {
            int n = tid >> 1, half = tid & 1;
            *(uint4*)&sBh[n][half * 4] = *(const uint4*)&Wph[n * 64 + kc * 8 + half * 4];
            *(uint4*)&sBl[n][half * 4] = *(const uint4*)&Wpl[n * 64 + kc * 8 + half * 4];
        }
        // stage A chunk: load fp32 float4, split bf16 hi/lo, store packed uint2
        {
            int r = tid >> 2, c4 = tid & 3;
            int gr = rowbase + r;
            float4 av = (gr < NN) ? ((const float4*)(A + gr * D + kc * 16))[c4]
                                  : make_float4(0.f, 0.f, 0.f, 0.f);
            __nv_bfloat16 hx = __float2bfloat16(av.x), hy = __float2bfloat16(av.y);
            __nv_bfloat16 hz = __float2bfloat16(av.z), hw = __float2bfloat16(av.w);
            uint2 hp = make_uint2(packbf2(__bfloat162float(hx), __bfloat162float(hy)),
                                  packbf2(__bfloat162float(hz), __bfloat162float(hw)));
            uint2 lp = make_uint2(packbf2(av.x - __bfloat162float(hx),
                                          av.y - __bfloat162float(hy)),
                                  packbf2(av.z - __bfloat162float(hz),
                                          av.w - __bfloat162float(hw)));
            *(uint2*)&sAh[r][c4 * 2] = hp;
            *(uint2*)&sAl[r][c4 * 2] = lp;
        }
        __syncthreads();

        uint32_t bh[2][2], bl[2][2];
        ldsm_x2(bh[0], aBh[0]);
        ldsm_x2(bh[1], aBh[1]);
        ldsm_x2(bl[0], aBl[0]);
        ldsm_x2(bl[1], aBl[1]);
#pragma unroll
        for (int mt = 0; mt < 4; mt++) {
            uint32_t ah[4], al[4];
            ldsm_x4(ah, aAh[mt]);
            ldsm_x4(al, aAl[mt]);
#pragma unroll
            for (int nt = 0; nt < 2; nt++) {
                mma_bf16(acc[mt][nt], al, bh[nt]);  // small terms first
                mma_bf16(acc[mt][nt], ah, bl[nt]);
                mma_bf16(acc[mt][nt], ah, bh[nt]);
            }
        }
        __syncthreads();
    }

    float tmax = -1e30f;
#pragma unroll
    for (int mt = 0; mt < 4; mt++) {
#pragma unroll
        for (int nt = 0; nt < 2; nt++) {
            int n = n0 + nt * 8 + t4 * 2;
            float2 bb = *(const float2*)&b[n];
            float2 o0 = make_float2(acc[mt][nt][0] + bb.x, acc[mt][nt][1] + bb.y);
            float2 o1 = make_float2(acc[mt][nt][2] + bb.x, acc[mt][nt][3] + bb.y);
            tmax = fmaxf(tmax, fmaxf(fmaxf(o0.x, o0.y), fmaxf(o1.x, o1.y)));
            int r = rowbase + mt * 16 + g;
            if (r < NN) *(float2*)&C[r * D + n] = o0;
            int r2 = r + 8;
            if (r2 < NN) *(float2*)&C[r2 * D + n] = o1;
        }
    }
#pragma unroll
    for (int off = 16; off; off >>= 1)
        tmax = fmaxf(tmax, __shfl_xor_sync(0xffffffff, tmax, off));
    if (lane == 0) atomicMax(&g_hmaxk[slot], fkey(tmax));
}

// ---------------- GENConv aggregation (R9 version — proven) ----------------
__global__ void k_agg(const float* __restrict__ We, const float* __restrict__ be,
                      int slot) {
    int v  = blockIdx.x;
    int c2 = threadIdx.x;            // 0..63 -> channels 2*c2, 2*c2+1
    __shared__ int   s_src[64];
    __shared__ float s_attr[64];
    int s = g_row[v], e = g_row[v + 1];
    float2 we2 = ((const float2*)We)[c2];
    float2 be2 = ((const float2*)be)[c2];
    const float L2E = 1.4426950408889634f;
    float hmax = fdec(g_hmaxk[slot]);
    float blx = (fmaxf(hmax + fmaxf(be2.x, we2.x + be2.x), 0.f) + EPSV) * L2E;
    float bly = (fmaxf(hmax + fmaxf(be2.y, we2.y + be2.y), 0.f) + EPSV) * L2E;
    float denx = 0.f, wsx = 0.f, deny = 0.f, wsy = 0.f;
    const float2* h2 = (const float2*)g_h;
    for (int base = s; base < e; base += 64) {
        int n = min(64, e - base);
        if (c2 < n) {
            s_src[c2]  = g_srcs[base + c2];
            s_attr[c2] = g_attrs[base + c2];
        }
        __syncthreads();
        for (int i = 0; i < n; i++) {
            float2 hv = h2[s_src[i] * 64 + c2];
            float a = s_attr[i];
            float mx = fmaxf(hv.x + fmaf(a, we2.x, be2.x), 0.f) + EPSV;
            float my = fmaxf(hv.y + fmaf(a, we2.y, be2.y), 0.f) + EPSV;
            float ex = ex2f(fmaf(mx, L2E, -blx));   // exp(mx - bound_x), <= 1
            float ey = ex2f(fmaf(my, L2E, -bly));
            denx += ex; wsx = fmaf(ex, mx, wsx);
            deny += ey; wsy = fmaf(ey, my, wsy);
        }
        __syncthreads();
    }
    float2 hself = h2[v * 64 + c2];
    float2 o;
    o.x = ((e > s) ? (wsx / denx) : 0.f) + hself.x;
    o.y = ((e > s) ? (wsy / deny) : 0.f) + hself.y;
    ((float2*)g_out)[v * 64 + c2] = o;
}

// ---------------- output head: out = h @ Wo + bo, one warp per node ----------------
__global__ void k_head(const float* __restrict__ Wo, const float* __restrict__ bo,
                       float* __restrict__ out) {
    int gw   = (blockIdx.x * blockDim.x + threadIdx.x) >> 5;
    int lane = threadIdx.x & 31;
    if (gw >= NN) return;
    float h0 = g_h[gw * D + lane];
    float h1 = g_h[gw * D + lane + 32];
    float h2 = g_h[gw * D + lane + 64];
    float h3 = g_h[gw * D + lane + 96];
#pragma unroll
    for (int o = 0; o < 3; o++) {
        float acc = h0 * __ldg(&Wo[lane * 3 + o]) + h1 * __ldg(&Wo[(lane + 32) * 3 + o]) +
                    h2 * __ldg(&Wo[(lane + 64) * 3 + o]) + h3 * __ldg(&Wo[(lane + 96) * 3 + o]);
#pragma unroll
        for (int off = 16; off; off >>= 1) acc += __shfl_down_sync(0xffffffff, acc, off);
        if (lane == 0) out[gw * 3 + o] = acc + bo[o];
    }
}

// ---------------- launch (first GEMM kept at launch idx 3 = profiled slot) ----------
extern "C" void kernel_launch(void* const* d_in, const int* in_sizes, int n_in,
                              void* d_out, int out_size) {
    const float* x    = (const float*)d_in[0];
    const int*   ei   = (const int*)d_in[1];   // [2, NE]
    const float* attr = (const float*)d_in[2];
    const float* Wn1  = (const float*)d_in[3];
    const float* bn1  = (const float*)d_in[4];
    const float* Wn2  = (const float*)d_in[5];
    const float* bn2  = (const float*)d_in[6];
    const float* We   = (const float*)d_in[7];
    const float* be   = (const float*)d_in[8];
    const float* Wg   = (const float*)d_in[9];  // [4,128,128]
    const float* bg   = (const float*)d_in[10]; // [4,128]
    const float* Wo   = (const float*)d_in[11];
    const float* bo   = (const float*)d_in[12];
    float* out = (float*)d_out;

    const int* src = ei;
    const int* dst = ei + NE;

    float* p_h;
    float* p_out;
    uint32_t* p_Wph;
    uint32_t* p_Wpl;
    cudaGetSymbolAddress((void**)&p_h, g_h);
    cudaGetSymbolAddress((void**)&p_out, g_out);
    cudaGetSymbolAddress((void**)&p_Wph, g_Wph);
    cudaGetSymbolAddress((void**)&p_Wpl, g_Wpl);

    int gblocks = (NN + TM - 1) / TM;

    // idx 0: encoder stage 1 (independent of CSR)
    k_enc1<<<NN, D>>>(x, Wn1, bn1);                    // g_out = relu(x@Wn1+bn1)
    // idx 1: CSR zero
    k_zero<<<(NN + 255) / 256, 256>>>();
    // idx 2: weight preconversion (needed before idx 3)
    k_prepW<<<((NL + 1) * D * D / 2 + 255) / 256, 256>>>(Wn2, Wg);
    // idx 3: encoder GEMM  <-- profiled slot
    k_gemm_bf<<<gblocks, 256>>>(p_out, p_Wph, p_Wpl, bn2, p_h, 0);
    // idx 4-8: CSR build finish
    k_hist<<<(NE + 255) / 256, 256>>>(dst);
    k_scan<<<1, 1024>>>();
    k_scatter<<<(NE + 255) / 256, 256>>>(dst);
    k_sort<<<(NN + 255) / 256, 256>>>();
    k_fill<<<(NE + 255) / 256, 256>>>(src, attr);

    // ---- 4 GENConv layers ----
    for (int l = 0; l < NL; l++) {
        k_agg<<<NN, 64>>>(We, be, l);  // g_out = agg + g_h, bound from slot l
        k_gemm_bf<<<gblocks, 256>>>(p_out, p_Wph + (l + 1) * D * D / 2,
                                    p_Wpl + (l + 1) * D * D / 2, bg + l * D, p_h, l + 1);
    }

    // ---- head ----
    k_head<<<(NN * 32 + 255) / 256, 256>>>(Wo, bo, out);
}

// round 12
// speedup vs baseline: 1.5874x; 1.0068x over previous
#include <cuda_runtime.h>
#include <cuda_bf16.h>
#include <math.h>
#include <stdint.h>

#define D   128
#define NN  30000
#define NE  480000
#define NL  4
#define EPSV 1e-7f

// ---------------- device scratch (static, no allocation) ----------------
__device__ float g_h[NN * D];        // current node features (fp32)
// A operand for GEMM, pre-split by producers: packed bf16 pairs [node][64]
__device__ uint32_t g_outh[NN * 64]; // hi parts (2 channels per uint32)
__device__ uint32_t g_outl[NN * 64]; // lo (residual) parts
__device__ int   g_srcs[NE];      // CSR-ordered source node per edge
__device__ float g_attrs[NE];     // CSR-ordered edge attr scalar per edge
__device__ int   g_eids[NE];      // CSR-ordered original edge ids (determinism sort key)
__device__ int   g_row[NN + 1];   // CSR row offsets
__device__ int   g_cur[NN];       // histogram / scatter cursor
// preconverted packed TRANSPOSED bf16 hi/lo weights: [m][n][k/2] uint32
__device__ uint32_t g_Wph[(NL + 1) * D * D / 2];
__device__ uint32_t g_Wpl[(NL + 1) * D * D / 2];
// global max of h per GEMM (order-preserving uint key); atomicMax idempotent across replays
__device__ unsigned g_hmaxk[NL + 1];

__device__ __forceinline__ unsigned fkey(float f) {
    unsigned u = __float_as_uint(f);
    return (u & 0x80000000u) ? ~u : (u | 0x80000000u);
}
__device__ __forceinline__ float fdec(unsigned k) {
    return (k & 0x80000000u) ? __uint_as_float(k & 0x7FFFFFFFu) : __uint_as_float(~k);
}
__device__ __forceinline__ float ex2f(float x) {
    float r;
    asm("ex2.approx.ftz.f32 %0, %1;" : "=f"(r) : "f"(x));
    return r;
}
__device__ __forceinline__ uint32_t packbf2(float lo, float hi) {
    __nv_bfloat162 t = __floats2bfloat162_rn(lo, hi);
    return *(uint32_t*)&t;
}
// split fp32 pair -> packed bf16 hi + packed bf16 residual
__device__ __forceinline__ void split2(float x, float y, uint32_t& hp, uint32_t& lp) {
    __nv_bfloat16 hx = __float2bfloat16(x), hy = __float2bfloat16(y);
    hp = packbf2(__bfloat162float(hx), __bfloat162float(hy));
    lp = packbf2(x - __bfloat162float(hx), y - __bfloat162float(hy));
}

// ---------------- CSR build ----------------
__global__ void k_zero() {
    int i = blockIdx.x * blockDim.x + threadIdx.x;
    if (i < NN) g_cur[i] = 0;
}

__global__ void k_hist(const int* __restrict__ dst) {
    int e = blockIdx.x * blockDim.x + threadIdx.x;
    if (e < NE) atomicAdd(&g_cur[dst[e]], 1);
}

__global__ void k_scan() {
    __shared__ int ssum[1024];
    int t = threadIdx.x;
    const int CH = (NN + 1023) / 1024;  // 30
    int base = t * CH;
    int s = 0;
    for (int i = 0; i < CH; i++) {
        int idx = base + i;
        if (idx < NN) s += g_cur[idx];
    }
    ssum[t] = s;
    __syncthreads();
    for (int off = 1; off < 1024; off <<= 1) {
        int v = (t >= off) ? ssum[t - off] : 0;
        __syncthreads();
        ssum[t] += v;
        __syncthreads();
    }
    int run = (t == 0) ? 0 : ssum[t - 1];
    for (int i = 0; i < CH; i++) {
        int idx = base + i;
        if (idx < NN) {
            int c = g_cur[idx];
            g_row[idx] = run;
            g_cur[idx] = run;
            run += c;
        }
    }
    if (t == 1023) g_row[NN] = run;
}

__global__ void k_scatter(const int* __restrict__ dst) {
    int e = blockIdx.x * blockDim.x + threadIdx.x;
    if (e >= NE) return;
    int d = dst[e];
    int pos = atomicAdd(&g_cur[d], 1);
    g_eids[pos] = e;
}

__global__ void k_sort() {
    int v = blockIdx.x * blockDim.x + threadIdx.x;
    if (v >= NN) return;
    int s = g_row[v], e = g_row[v + 1];
    for (int i = s + 1; i < e; i++) {
        int key = g_eids[i];
        int j = i - 1;
        while (j >= s && g_eids[j] > key) {
            g_eids[j + 1] = g_eids[j];
            j--;
        }
        g_eids[j + 1] = key;
    }
}

__global__ void k_fill(const int* __restrict__ src, const float* __restrict__ attr) {
    int p = blockIdx.x * blockDim.x + threadIdx.x;
    if (p >= NE) return;
    int e = g_eids[p];
    g_srcs[p]  = src[e];
    g_attrs[p] = attr[e];
}

// ---------------- node encoder stage 1: relu(x @ Wn1 + bn1) -> packed bf16 hi/lo ----
__global__ void k_enc1(const float* __restrict__ x, const float* __restrict__ Wn1,
                       const float* __restrict__ bn1) {
    int v  = blockIdx.x;
    int c2 = threadIdx.x;  // 64 threads, 2 channels each
    __shared__ float sx[7];
    if (c2 < 7) sx[c2] = x[v * 7 + c2];
    __syncthreads();
    int c0 = 2 * c2;
    float a0 = bn1[c0], a1 = bn1[c0 + 1];
#pragma unroll
    for (int k = 0; k < 7; k++) {
        a0 += sx[k] * Wn1[k * D + c0];
        a1 += sx[k] * Wn1[k * D + c0 + 1];
    }
    a0 = fmaxf(a0, 0.f);
    a1 = fmaxf(a1, 0.f);
    uint32_t hp, lp;
    split2(a0, a1, hp, lp);
    g_outh[v * 64 + c2] = hp;
    g_outl[v * 64 + c2] = lp;
}

// ---------------- weight preconversion: W -> packed transposed bf16 hi/lo --------
__global__ void k_prepW(const float* __restrict__ Wn2, const float* __restrict__ Wg) {
    int i = blockIdx.x * blockDim.x + threadIdx.x;  // (NL+1)*D*D/2 = 40960
    if (i >= (NL + 1) * D * D / 2) return;
    int m   = i >> 13;
    int rem = i & 8191;
    int n   = rem >> 6;
    int kk  = rem & 63;
    const float* W = (m == 0) ? Wn2 : (Wg + (m - 1) * D * D);
    float w0 = W[(2 * kk) * D + n];
    float w1 = W[(2 * kk + 1) * D + n];
    uint32_t hp, lp;
    split2(w0, w1, hp, lp);
    g_Wph[i] = hp;
    g_Wpl[i] = lp;
}

// ---------------- tensor-core 64x128 Linear (2-term bf16, ldmatrix, cp.async x2buf) --
// A arrives pre-split (g_outh/g_outl): ALL staging is pure 16B cp.async copies,
// double-buffered so chunk k+1 loads overlap chunk k's MMAs (R11: staging+LDSM
// saturated L1 with issue only 16% -- latency exposed each chunk).
__device__ __forceinline__ void mma_bf16(float* c, const uint32_t* a, const uint32_t* b) {
    asm volatile(
        "mma.sync.aligned.m16n8k16.row.col.f32.bf16.bf16.f32 "
        "{%0,%1,%2,%3}, {%4,%5,%6,%7}, {%8,%9}, {%0,%1,%2,%3};"
        : "+f"(c[0]), "+f"(c[1]), "+f"(c[2]), "+f"(c[3])
        : "r"(a[0]), "r"(a[1]), "r"(a[2]), "r"(a[3]), "r"(b[0]), "r"(b[1]));
}
__device__ __forceinline__ void ldsm_x4(uint32_t* r, uint32_t addr) {
    asm volatile("ldmatrix.sync.aligned.m8n8.x4.shared.b16 {%0,%1,%2,%3}, [%4];"
                 : "=r"(r[0]), "=r"(r[1]), "=r"(r[2]), "=r"(r[3]) : "r"(addr));
}
__device__ __forceinline__ void ldsm_x2(uint32_t* r, uint32_t addr) {
    asm volatile("ldmatrix.sync.aligned.m8n8.x2.shared.b16 {%0,%1}, [%2];"
                 : "=r"(r[0]), "=r"(r[1]) : "r"(addr));
}
__device__ __forceinline__ void cpa16(uint32_t d, const void* s, uint32_t sz) {
    asm volatile("cp.async.cg.shared.global [%0], [%1], 16, %2;"
                 :: "r"(d), "l"(s), "r"(sz) : "memory");
}
__device__ __forceinline__ void cpcommit() {
    asm volatile("cp.async.commit_group;" ::: "memory");
}
template <int N>
__device__ __forceinline__ void cpwait() {
    asm volatile("cp.async.wait_group %0;" :: "n"(N) : "memory");
}

#define TM 64   // rows per block
#define ABUF (TM * 12 * 4)   // byte offset between A buffers
#define BBUF (D * 12 * 4)    // byte offset between B buffers

__global__ __launch_bounds__(256, 2) void k_gemm_bf(const uint32_t* __restrict__ Aph,
                                                    const uint32_t* __restrict__ Apl,
                                                    const uint32_t* __restrict__ Wph,
                                                    const uint32_t* __restrict__ Wpl,
                                                    const float* __restrict__ b,
                                                    float* __restrict__ C, int slot) {
    __shared__ uint32_t sBh[2][D][12], sBl[2][D][12];   // [buf][n][k-chunk], cols 0..7
    __shared__ uint32_t sAh[2][TM][12], sAl[2][TM][12];
    int tid  = threadIdx.x;          // 256
    int w    = tid >> 5;
    int lane = tid & 31;
    int g    = lane >> 2;
    int t4   = lane & 3;
    int rowbase = blockIdx.x * TM;
    int n0 = w * 16;

    // ---- staging map: 3 cp.async per thread per chunk ----
    int nW = tid >> 1, hW = tid & 1;        // W: 128 n x 2 halves (for hi and lo)
    int isLo = tid >= 128;                  // A: first 128 threads hi, rest lo
    int rA = (tid & 127) >> 1, hA = tid & 1;
    int grA = rowbase + rA;
    uint32_t szA = (grA < NN) ? 16u : 0u;   // zero-fill OOB rows
    const uint32_t* gWh = Wph + nW * 64 + hW * 4;
    const uint32_t* gWl = Wpl + nW * 64 + hW * 4;
    const uint32_t* gA  = (isLo ? Apl : Aph) + (size_t)grA * 64 + hA * 4;
    uint32_t dWh0 = (uint32_t)__cvta_generic_to_shared(&sBh[0][nW][hW * 4]);
    uint32_t dWl0 = (uint32_t)__cvta_generic_to_shared(&sBl[0][nW][hW * 4]);
    uint32_t dA0  = (uint32_t)__cvta_generic_to_shared(
        isLo ? &sAl[0][rA][hA * 4] : &sAh[0][rA][hA * 4]);

    // ---- ldmatrix lane addresses (buffer 0; add buf offset at use) ----
    int lr    = lane & 7;
    int lhalf = (lane >> 3) & 1;
    int lcol  = (lane >> 4) * 4;
    uint32_t aAh[4], aAl[4], aBh[2], aBl[2];
#pragma unroll
    for (int mt = 0; mt < 4; mt++) {
        int r = mt * 16 + lhalf * 8 + lr;
        aAh[mt] = (uint32_t)__cvta_generic_to_shared(&sAh[0][r][lcol]);
        aAl[mt] = (uint32_t)__cvta_generic_to_shared(&sAl[0][r][lcol]);
    }
#pragma unroll
    for (int nt = 0; nt < 2; nt++) {
        int r = n0 + nt * 8 + lr;
        aBh[nt] = (uint32_t)__cvta_generic_to_shared(&sBh[0][r][lhalf * 4]);
        aBl[nt] = (uint32_t)__cvta_generic_to_shared(&sBl[0][r][lhalf * 4]);
    }

    float acc[4][2][4];
#pragma unroll
    for (int mt = 0; mt < 4; mt++)
#pragma unroll
        for (int nt = 0; nt < 2; nt++)
#pragma unroll
            for (int i = 0; i < 4; i++) acc[mt][nt][i] = 0.f;

    // prefetch chunk 0 into buffer 0
    cpa16(dWh0, gWh, 16);
    cpa16(dWl0, gWl, 16);
    cpa16(dA0, gA, szA);
    cpcommit();

#pragma unroll
    for (int kc = 0; kc < 8; kc++) {
        int cur = kc & 1;
        if (kc < 7) {
            int nxt = cur ^ 1;
            cpa16(dWh0 + nxt * BBUF, gWh + (kc + 1) * 8, 16);
            cpa16(dWl0 + nxt * BBUF, gWl + (kc + 1) * 8, 16);
            cpa16(dA0 + nxt * ABUF, gA + (kc + 1) * 8, szA);
            cpcommit();
            cpwait<1>();   // chunk kc's group done; kc+1 in flight
        } else {
            cpwait<0>();
        }
        __syncthreads();

        uint32_t bofA = cur * ABUF, bofB = cur * BBUF;
        uint32_t bh[2][2], bl[2][2];
        ldsm_x2(bh[0], aBh[0] + bofB);
        ldsm_x2(bh[1], aBh[1] + bofB);
        ldsm_x2(bl[0], aBl[0] + bofB);
        ldsm_x2(bl[1], aBl[1] + bofB);
#pragma unroll
        for (int mt = 0; mt < 4; mt++) {
            uint32_t ah[4], al[4];
            ldsm_x4(ah, aAh[mt] + bofA);
            ldsm_x4(al, aAl[mt] + bofA);
#pragma unroll
            for (int nt = 0; nt < 2; nt++) {
                mma_bf16(acc[mt][nt], al, bh[nt]);  // small terms first
                mma_bf16(acc[mt][nt], ah, bl[nt]);
                mma_bf16(acc[mt][nt], ah, bh[nt]);
            }
        }
        __syncthreads();
    }

    float tmax = -1e30f;
#pragma unroll
    for (int mt = 0; mt < 4; mt++) {
#pragma unroll
        for (int nt = 0; nt < 2; nt++) {
            int n = n0 + nt * 8 + t4 * 2;
            float2 bb = *(const float2*)&b[n];
            float2 o0 = make_float2(acc[mt][nt][0] + bb.x, acc[mt][nt][1] + bb.y);
            float2 o1 = make_float2(acc[mt][nt][2] + bb.x, acc[mt][nt][3] + bb.y);
            tmax = fmaxf(tmax, fmaxf(fmaxf(o0.x, o0.y), fmaxf(o1.x, o1.y)));
            int r = rowbase + mt * 16 + g;
            if (r < NN) *(float2*)&C[r * D + n] = o0;
            int r2 = r + 8;
            if (r2 < NN) *(float2*)&C[r2 * D + n] = o1;
        }
    }
#pragma unroll
    for (int off = 16; off; off >>= 1)
        tmax = fmaxf(tmax, __shfl_xor_sync(0xffffffff, tmax, off));
    if (lane == 0) atomicMax(&g_hmaxk[slot], fkey(tmax));
}

// ---------------- GENConv aggregation (bound-shifted softmax; packed bf16 output) ----
__global__ void k_agg(const float* __restrict__ We, const float* __restrict__ be,
                      int slot) {
    int v  = blockIdx.x;
    int c2 = threadIdx.x;            // 0..63 -> channels 2*c2, 2*c2+1
    __shared__ int   s_src[64];
    __shared__ float s_attr[64];
    int s = g_row[v], e = g_row[v + 1];
    float2 we2 = ((const float2*)We)[c2];
    float2 be2 = ((const float2*)be)[c2];
    const float L2E = 1.4426950408889634f;
    float hmax = fdec(g_hmaxk[slot]);
    float blx = (fmaxf(hmax + fmaxf(be2.x, we2.x + be2.x), 0.f) + EPSV) * L2E;
    float bly = (fmaxf(hmax + fmaxf(be2.y, we2.y + be2.y), 0.f) + EPSV) * L2E;
    float denx = 0.f, wsx = 0.f, deny = 0.f, wsy = 0.f;
    const float2* h2 = (const float2*)g_h;
    for (int base = s; base < e; base += 64) {
        int n = min(64, e - base);
        if (c2 < n) {
            s_src[c2]  = g_srcs[base + c2];
            s_attr[c2] = g_attrs[base + c2];
        }
        __syncthreads();
        for (int i = 0; i < n; i++) {
            float2 hv = h2[s_src[i] * 64 + c2];
            float a = s_attr[i];
            float mx = fmaxf(hv.x + fmaf(a, we2.x, be2.x), 0.f) + EPSV;
            float my = fmaxf(hv.y + fmaf(a, we2.y, be2.y), 0.f) + EPSV;
            float ex = ex2f(fmaf(mx, L2E, -blx));   // exp(mx - bound_x), <= 1
            float ey = ex2f(fmaf(my, L2E, -bly));
            denx += ex; wsx = fmaf(ex, mx, wsx);
            deny += ey; wsy = fmaf(ey, my, wsy);
        }
        __syncthreads();
    }
    float2 hself = h2[v * 64 + c2];
    float ox = ((e > s) ? (wsx / denx) : 0.f) + hself.x;
    float oy = ((e > s) ? (wsy / deny) : 0.f) + hself.y;
    uint32_t hp, lp;
    split2(ox, oy, hp, lp);
    g_outh[v * 64 + c2] = hp;
    g_outl[v * 64 + c2] = lp;
}

// ---------------- output head: out = h @ Wo + bo, one warp per node ----------------
__global__ void k_head(const float* __restrict__ Wo, const float* __restrict__ bo,
                       float* __restrict__ out) {
    int gw   = (blockIdx.x * blockDim.x + threadIdx.x) >> 5;
    int lane = threadIdx.x & 31;
    if (gw >= NN) return;
    float h0 = g_h[gw * D + lane];
    float h1 = g_h[gw * D + lane + 32];
    float h2 = g_h[gw * D + lane + 64];
    float h3 = g_h[gw * D + lane + 96];
#pragma unroll
    for (int o = 0; o < 3; o++) {
        float acc = h0 * __ldg(&Wo[lane * 3 + o]) + h1 * __ldg(&Wo[(lane + 32) * 3 + o]) +
                    h2 * __ldg(&Wo[(lane + 64) * 3 + o]) + h3 * __ldg(&Wo[(lane + 96) * 3 + o]);
#pragma unroll
        for (int off = 16; off; off >>= 1) acc += __shfl_down_sync(0xffffffff, acc, off);
        if (lane == 0) out[gw * 3 + o] = acc + bo[o];
    }
}

// ---------------- launch (first GEMM kept at launch idx 3 = profiled slot) ----------
extern "C" void kernel_launch(void* const* d_in, const int* in_sizes, int n_in,
                              void* d_out, int out_size) {
    const float* x    = (const float*)d_in[0];
    const int*   ei   = (const int*)d_in[1];   // [2, NE]
    const float* attr = (const float*)d_in[2];
    const float* Wn1  = (const float*)d_in[3];
    const float* bn1  = (const float*)d_in[4];
    const float* Wn2  = (const float*)d_in[5];
    const float* bn2  = (const float*)d_in[6];
    const float* We   = (const float*)d_in[7];
    const float* be   = (const float*)d_in[8];
    const float* Wg   = (const float*)d_in[9];  // [4,128,128]
    const float* bg   = (const float*)d_in[10]; // [4,128]
    const float* Wo   = (const float*)d_in[11];
    const float* bo   = (const float*)d_in[12];
    float* out = (float*)d_out;

    const int* src = ei;
    const int* dst = ei + NE;

    float* p_h;
    uint32_t* p_outh;
    uint32_t* p_outl;
    uint32_t* p_Wph;
    uint32_t* p_Wpl;
    cudaGetSymbolAddress((void**)&p_h, g_h);
    cudaGetSymbolAddress((void**)&p_outh, g_outh);
    cudaGetSymbolAddress((void**)&p_outl, g_outl);
    cudaGetSymbolAddress((void**)&p_Wph, g_Wph);
    cudaGetSymbolAddress((void**)&p_Wpl, g_Wpl);

    int gblocks = (NN + TM - 1) / TM;

    // idx 0: encoder stage 1 (independent of CSR)
    k_enc1<<<NN, 64>>>(x, Wn1, bn1);            // g_outh/l = split(relu(x@Wn1+bn1))
    // idx 1: CSR zero
    k_zero<<<(NN + 255) / 256, 256>>>();
    // idx 2: weight preconversion (needed before idx 3)
    k_prepW<<<((NL + 1) * D * D / 2 + 255) / 256, 256>>>(Wn2, Wg);
    // idx 3: encoder GEMM  <-- profiled slot
    k_gemm_bf<<<gblocks, 256>>>(p_outh, p_outl, p_Wph, p_Wpl, bn2, p_h, 0);
    // idx 4-8: CSR build finish
    k_hist<<<(NE + 255) / 256, 256>>>(dst);
    k_scan<<<1, 1024>>>();
    k_scatter<<<(NE + 255) / 256, 256>>>(dst);
    k_sort<<<(NN + 255) / 256, 256>>>();
    k_fill<<<(NE + 255) / 256, 256>>>(src, attr);

    // ---- 4 GENConv layers ----
    for (int l = 0; l < NL; l++) {
        k_agg<<<NN, 64>>>(We, be, l);  // g_outh/l = split(agg + g_h)
        k_gemm_bf<<<gblocks, 256>>>(p_outh, p_outl, p_Wph + (l + 1) * D * D / 2,
                                    p_Wpl + (l + 1) * D * D / 2, bg + l * D, p_h, l + 1);
    }

    // ---- head ----
    k_head<<<(NN * 32 + 255) / 256, 256>>>(Wo, bo, out);
}

// round 13
// speedup vs baseline: 1.6226x; 1.0221x over previous
#include <cuda_runtime.h>
#include <cuda_bf16.h>
#include <math.h>
#include <stdint.h>

#define D   128
#define NN  30000
#define NE  480000
#define NL  4
#define EPSV 1e-7f

// ---------------- device scratch (static, no allocation) ----------------
__device__ float g_h[NN * D];        // current node features (fp32)
// A operand for GEMM, pre-split by producers: packed bf16 pairs [node][64]
__device__ uint32_t g_outh[NN * 64]; // hi parts (2 channels per uint32)
__device__ uint32_t g_outl[NN * 64]; // lo (residual) parts
__device__ int   g_srcs[NE];      // CSR-ordered source node per edge
__device__ float g_attrs[NE];     // CSR-ordered edge attr scalar per edge
__device__ int   g_eids[NE];      // CSR-ordered original edge ids (determinism sort key)
__device__ int   g_row[NN + 1];   // CSR row offsets
__device__ int   g_cur[NN];       // histogram / scatter cursor
// preconverted packed TRANSPOSED bf16 hi/lo weights: [m][n][k/2] uint32
__device__ uint32_t g_Wph[(NL + 1) * D * D / 2];
__device__ uint32_t g_Wpl[(NL + 1) * D * D / 2];
// global max of h per GEMM (order-preserving uint key); atomicMax idempotent across replays
__device__ unsigned g_hmaxk[NL + 1];

__device__ __forceinline__ unsigned fkey(float f) {
    unsigned u = __float_as_uint(f);
    return (u & 0x80000000u) ? ~u : (u | 0x80000000u);
}
__device__ __forceinline__ float fdec(unsigned k) {
    return (k & 0x80000000u) ? __uint_as_float(k & 0x7FFFFFFFu) : __uint_as_float(~k);
}
__device__ __forceinline__ float ex2f(float x) {
    float r;
    asm("ex2.approx.ftz.f32 %0, %1;" : "=f"(r) : "f"(x));
    return r;
}
__device__ __forceinline__ uint32_t packbf2(float lo, float hi) {
    __nv_bfloat162 t = __floats2bfloat162_rn(lo, hi);
    return *(uint32_t*)&t;
}
__device__ __forceinline__ void split2(float x, float y, uint32_t& hp, uint32_t& lp) {
    __nv_bfloat16 hx = __float2bfloat16(x), hy = __float2bfloat16(y);
    hp = packbf2(__bfloat162float(hx), __bfloat162float(hy));
    lp = packbf2(x - __bfloat162float(hx), y - __bfloat162float(hy));
}

// ---------------- CSR build ----------------
__global__ void k_zero() {
    int i = blockIdx.x * blockDim.x + threadIdx.x;
    if (i < NN) g_cur[i] = 0;
}

__global__ void k_hist(const int* __restrict__ dst) {
    int e = blockIdx.x * blockDim.x + threadIdx.x;
    if (e < NE) atomicAdd(&g_cur[dst[e]], 1);
}

__global__ void k_scan() {
    __shared__ int ssum[1024];
    int t = threadIdx.x;
    const int CH = (NN + 1023) / 1024;  // 30
    int base = t * CH;
    int s = 0;
    for (int i = 0; i < CH; i++) {
        int idx = base + i;
        if (idx < NN) s += g_cur[idx];
    }
    ssum[t] = s;
    __syncthreads();
    for (int off = 1; off < 1024; off <<= 1) {
        int v = (t >= off) ? ssum[t - off] : 0;
        __syncthreads();
        ssum[t] += v;
        __syncthreads();
    }
    int run = (t == 0) ? 0 : ssum[t - 1];
    for (int i = 0; i < CH; i++) {
        int idx = base + i;
        if (idx < NN) {
            int c = g_cur[idx];
            g_row[idx] = run;
            g_cur[idx] = run;
            run += c;
        }
    }
    if (t == 1023) g_row[NN] = run;
}

__global__ void k_scatter(const int* __restrict__ dst) {
    int e = blockIdx.x * blockDim.x + threadIdx.x;
    if (e >= NE) return;
    int d = dst[e];
    int pos = atomicAdd(&g_cur[d], 1);
    g_eids[pos] = e;
}

__global__ void k_sort() {
    int v = blockIdx.x * blockDim.x + threadIdx.x;
    if (v >= NN) return;
    int s = g_row[v], e = g_row[v + 1];
    for (int i = s + 1; i < e; i++) {
        int key = g_eids[i];
        int j = i - 1;
        while (j >= s && g_eids[j] > key) {
            g_eids[j + 1] = g_eids[j];
            j--;
        }
        g_eids[j + 1] = key;
    }
}

__global__ void k_fill(const int* __restrict__ src, const float* __restrict__ attr) {
    int p = blockIdx.x * blockDim.x + threadIdx.x;
    if (p >= NE) return;
    int e = g_eids[p];
    g_srcs[p]  = src[e];
    g_attrs[p] = attr[e];
}

// ---------------- node encoder stage 1: relu(x @ Wn1 + bn1) -> packed bf16 hi/lo ----
__global__ void k_enc1(const float* __restrict__ x, const float* __restrict__ Wn1,
                       const float* __restrict__ bn1) {
    int v  = blockIdx.x;
    int c2 = threadIdx.x;  // 64 threads, 2 channels each
    __shared__ float sx[7];
    if (c2 < 7) sx[c2] = x[v * 7 + c2];
    __syncthreads();
    int c0 = 2 * c2;
    float a0 = bn1[c0], a1 = bn1[c0 + 1];
#pragma unroll
    for (int k = 0; k < 7; k++) {
        a0 += sx[k] * Wn1[k * D + c0];
        a1 += sx[k] * Wn1[k * D + c0 + 1];
    }
    a0 = fmaxf(a0, 0.f);
    a1 = fmaxf(a1, 0.f);
    uint32_t hp, lp;
    split2(a0, a1, hp, lp);
    g_outh[v * 64 + c2] = hp;
    g_outl[v * 64 + c2] = lp;
}

// ---------------- weight preconversion: W -> packed transposed bf16 hi/lo --------
__global__ void k_prepW(const float* __restrict__ Wn2, const float* __restrict__ Wg) {
    int i = blockIdx.x * blockDim.x + threadIdx.x;  // (NL+1)*D*D/2 = 40960
    if (i >= (NL + 1) * D * D / 2) return;
    int m   = i >> 13;
    int rem = i & 8191;
    int n   = rem >> 6;
    int kk  = rem & 63;
    const float* W = (m == 0) ? Wn2 : (Wg + (m - 1) * D * D);
    float w0 = W[(2 * kk) * D + n];
    float w1 = W[(2 * kk + 1) * D + n];
    uint32_t hp, lp;
    split2(w0, w1, hp, lp);
    g_Wph[i] = hp;
    g_Wpl[i] = lp;
}

// ---------------- tensor-core 64x128 Linear: single-stage full-tile smem ----------
// R12 showed issue=13.3%: 17 block-wide sync points around the 8 k-chunks were
// the binder. Now the ENTIRE tile (A 32KB + W 70KB, stride-68 rows) is staged
// with one cp.async burst + ONE syncthreads; all 8 chunks of LDSM+MMA then run
// with zero further synchronization. 4-word row spacing tiles all 32 banks.
__device__ __forceinline__ void mma_bf16(float* c, const uint32_t* a, const uint32_t* b) {
    asm volatile(
        "mma.sync.aligned.m16n8k16.row.col.f32.bf16.bf16.f32 "
        "{%0,%1,%2,%3}, {%4,%5,%6,%7}, {%8,%9}, {%0,%1,%2,%3};"
        : "+f"(c[0]), "+f"(c[1]), "+f"(c[2]), "+f"(c[3])
        : "r"(a[0]), "r"(a[1]), "r"(a[2]), "r"(a[3]), "r"(b[0]), "r"(b[1]));
}
__device__ __forceinline__ void ldsm_x4(uint32_t* r, uint32_t addr) {
    asm volatile("ldmatrix.sync.aligned.m8n8.x4.shared.b16 {%0,%1,%2,%3}, [%4];"
                 : "=r"(r[0]), "=r"(r[1]), "=r"(r[2]), "=r"(r[3]) : "r"(addr));
}
__device__ __forceinline__ void ldsm_x2(uint32_t* r, uint32_t addr) {
    asm volatile("ldmatrix.sync.aligned.m8n8.x2.shared.b16 {%0,%1}, [%2];"
                 : "=r"(r[0]), "=r"(r[1]) : "r"(addr));
}
__device__ __forceinline__ void cpa16(uint32_t d, const void* s, uint32_t sz) {
    asm volatile("cp.async.cg.shared.global [%0], [%1], 16, %2;"
                 :: "r"(d), "l"(s), "r"(sz) : "memory");
}
__device__ __forceinline__ void cpcommit() {
    asm volatile("cp.async.commit_group;" ::: "memory");
}
template <int N>
__device__ __forceinline__ void cpwait() {
    asm volatile("cp.async.wait_group %0;" :: "n"(N) : "memory");
}

#define TM 64   // rows per block
#define SW 68   // uint32 stride per smem row (64 data + 4 pad)
#define OA_H 0
#define OA_L (TM * SW * 4)
#define OB_H (2 * TM * SW * 4)
#define OB_L (2 * TM * SW * 4 + D * SW * 4)
#define GSMEM (2 * TM * SW * 4 + 2 * D * SW * 4)   // 104448 bytes

__global__ __launch_bounds__(256, 2) void k_gemm_bf(const uint32_t* __restrict__ Aph,
                                                    const uint32_t* __restrict__ Apl,
                                                    const uint32_t* __restrict__ Wph,
                                                    const uint32_t* __restrict__ Wpl,
                                                    const float* __restrict__ b,
                                                    float* __restrict__ C, int slot) {
    extern __shared__ uint32_t smem[];
    uint32_t dbase = (uint32_t)__cvta_generic_to_shared(smem);
    int tid  = threadIdx.x;          // 256
    int w    = tid >> 5;
    int lane = tid & 31;
    int g    = lane >> 2;
    int t4   = lane & 3;
    int rowbase = blockIdx.x * TM;
    int n0 = w * 16;

    // ---- stage entire tile: 6144 x 16B cp.async, 24 per thread, one group ----
    for (int it = tid; it < 6144; it += 256) {
        const uint32_t* src;
        uint32_t dst, sz = 16;
        if (it < 2048) {                       // A (hi then lo)
            int h  = it >> 10;
            int r  = (it & 1023) >> 4, kc = it & 15;
            int gr = rowbase + r;
            src = (h ? Apl : Aph) + (size_t)gr * 64 + kc * 4;
            dst = dbase + (h ? OA_L : OA_H) + (r * SW + kc * 4) * 4;
            if (gr >= NN) sz = 0;              // zero-fill OOB rows
        } else {                               // W (hi then lo)
            int t  = it - 2048;
            int h  = t >> 11;
            int r  = (t & 2047) >> 4, kc = t & 15;
            src = (h ? Wpl : Wph) + r * 64 + kc * 4;
            dst = dbase + (h ? OB_L : OB_H) + (r * SW + kc * 4) * 4;
        }
        cpa16(dst, src, sz);
    }
    cpcommit();

    // ---- ldmatrix lane addresses (chunk 0; +kc*32B per chunk) ----
    int lr    = lane & 7;
    int lhalf = (lane >> 3) & 1;
    int lcol  = (lane >> 4) * 4;
    uint32_t aAh[4], aAl[4], aBh[2], aBl[2];
#pragma unroll
    for (int mt = 0; mt < 4; mt++) {
        int r = mt * 16 + lhalf * 8 + lr;
        aAh[mt] = dbase + OA_H + (r * SW + lcol) * 4;
        aAl[mt] = dbase + OA_L + (r * SW + lcol) * 4;
    }
#pragma unroll
    for (int nt = 0; nt < 2; nt++) {
        int r = n0 + nt * 8 + lr;
        aBh[nt] = dbase + OB_H + (r * SW + lhalf * 4) * 4;
        aBl[nt] = dbase + OB_L + (r * SW + lhalf * 4) * 4;
    }

    float acc[4][2][4];
#pragma unroll
    for (int mt = 0; mt < 4; mt++)
#pragma unroll
        for (int nt = 0; nt < 2; nt++)
#pragma unroll
            for (int i = 0; i < 4; i++) acc[mt][nt][i] = 0.f;

    cpwait<0>();
    __syncthreads();   // the ONLY barrier

#pragma unroll
    for (int kc = 0; kc < 8; kc++) {
        uint32_t off = kc * 32;
        uint32_t bh[2][2], bl[2][2];
        ldsm_x2(bh[0], aBh[0] + off);
        ldsm_x2(bh[1], aBh[1] + off);
        ldsm_x2(bl[0], aBl[0] + off);
        ldsm_x2(bl[1], aBl[1] + off);
#pragma unroll
        for (int mt = 0; mt < 4; mt++) {
            uint32_t ah[4], al[4];
            ldsm_x4(ah, aAh[mt] + off);
            ldsm_x4(al, aAl[mt] + off);
#pragma unroll
            for (int nt = 0; nt < 2; nt++) {
                mma_bf16(acc[mt][nt], al, bh[nt]);  // small terms first
                mma_bf16(acc[mt][nt], ah, bl[nt]);
                mma_bf16(acc[mt][nt], ah, bh[nt]);
            }
        }
    }

    float tmax = -1e30f;
#pragma unroll
    for (int mt = 0; mt < 4; mt++) {
#pragma unroll
        for (int nt = 0; nt < 2; nt++) {
            int n = n0 + nt * 8 + t4 * 2;
            float2 bb = *(const float2*)&b[n];
            float2 o0 = make_float2(acc[mt][nt][0] + bb.x, acc[mt][nt][1] + bb.y);
            float2 o1 = make_float2(acc[mt][nt][2] + bb.x, acc[mt][nt][3] + bb.y);
            tmax = fmaxf(tmax, fmaxf(fmaxf(o0.x, o0.y), fmaxf(o1.x, o1.y)));
            int r = rowbase + mt * 16 + g;
            if (r < NN) *(float2*)&C[r * D + n] = o0;
            int r2 = r + 8;
            if (r2 < NN) *(float2*)&C[r2 * D + n] = o1;
        }
    }
#pragma unroll
    for (int off = 16; off; off >>= 1)
        tmax = fmaxf(tmax, __shfl_xor_sync(0xffffffff, tmax, off));
    if (lane == 0) atomicMax(&g_hmaxk[slot], fkey(tmax));
}

// ---------------- GENConv aggregation (bound-shifted softmax; packed bf16 output) ----
__global__ void k_agg(const float* __restrict__ We, const float* __restrict__ be,
                      int slot) {
    int v  = blockIdx.x;
    int c2 = threadIdx.x;            // 0..63 -> channels 2*c2, 2*c2+1
    __shared__ int   s_src[64];
    __shared__ float s_attr[64];
    int s = g_row[v], e = g_row[v + 1];
    float2 we2 = ((const float2*)We)[c2];
    float2 be2 = ((const float2*)be)[c2];
    const float L2E = 1.4426950408889634f;
    float hmax = fdec(g_hmaxk[slot]);
    float blx = (fmaxf(hmax + fmaxf(be2.x, we2.x + be2.x), 0.f) + EPSV) * L2E;
    float bly = (fmaxf(hmax + fmaxf(be2.y, we2.y + be2.y), 0.f) + EPSV) * L2E;
    float denx = 0.f, wsx = 0.f, deny = 0.f, wsy = 0.f;
    const float2* h2 = (const float2*)g_h;
    for (int base = s; base < e; base += 64) {
        int n = min(64, e - base);
        if (c2 < n) {
            s_src[c2]  = g_srcs[base + c2];
            s_attr[c2] = g_attrs[base + c2];
        }
        __syncthreads();
        for (int i = 0; i < n; i++) {
            float2 hv = h2[s_src[i] * 64 + c2];
            float a = s_attr[i];
            float mx = fmaxf(hv.x + fmaf(a, we2.x, be2.x), 0.f) + EPSV;
            float my = fmaxf(hv.y + fmaf(a, we2.y, be2.y), 0.f) + EPSV;
            float ex = ex2f(fmaf(mx, L2E, -blx));   // exp(mx - bound_x), <= 1
            float ey = ex2f(fmaf(my, L2E, -bly));
            denx += ex; wsx = fmaf(ex, mx, wsx);
            deny += ey; wsy = fmaf(ey, my, wsy);
        }
        __syncthreads();
    }
    float2 hself = h2[v * 64 + c2];
    float ox = ((e > s) ? (wsx / denx) : 0.f) + hself.x;
    float oy = ((e > s) ? (wsy / deny) : 0.f) + hself.y;
    uint32_t hp, lp;
    split2(ox, oy, hp, lp);
    g_outh[v * 64 + c2] = hp;
    g_outl[v * 64 + c2] = lp;
}

// ---------------- output head: out = h @ Wo + bo, one warp per node ----------------
__global__ void k_head(const float* __restrict__ Wo, const float* __restrict__ bo,
                       float* __restrict__ out) {
    int gw   = (blockIdx.x * blockDim.x + threadIdx.x) >> 5;
    int lane = threadIdx.x & 31;
    if (gw >= NN) return;
    float h0 = g_h[gw * D + lane];
    float h1 = g_h[gw * D + lane + 32];
    float h2 = g_h[gw * D + lane + 64];
    float h3 = g_h[gw * D + lane + 96];
#pragma unroll
    for (int o = 0; o < 3; o++) {
        float acc = h0 * __ldg(&Wo[lane * 3 + o]) + h1 * __ldg(&Wo[(lane + 32) * 3 + o]) +
                    h2 * __ldg(&Wo[(lane + 64) * 3 + o]) + h3 * __ldg(&Wo[(lane + 96) * 3 + o]);
#pragma unroll
        for (int off = 16; off; off >>= 1) acc += __shfl_down_sync(0xffffffff, acc, off);
        if (lane == 0) out[gw * 3 + o] = acc + bo[o];
    }
}

// ---------------- launch (first GEMM kept at launch idx 3 = profiled slot) ----------
extern "C" void kernel_launch(void* const* d_in, const int* in_sizes, int n_in,
                              void* d_out, int out_size) {
    const float* x    = (const float*)d_in[0];
    const int*   ei   = (const int*)d_in[1];   // [2, NE]
    const float* attr = (const float*)d_in[2];
    const float* Wn1  = (const float*)d_in[3];
    const float* bn1  = (const float*)d_in[4];
    const float* Wn2  = (const float*)d_in[5];
    const float* bn2  = (const float*)d_in[6];
    const float* We   = (const float*)d_in[7];
    const float* be   = (const float*)d_in[8];
    const float* Wg   = (const float*)d_in[9];  // [4,128,128]
    const float* bg   = (const float*)d_in[10]; // [4,128]
    const float* Wo   = (const float*)d_in[11];
    const float* bo   = (const float*)d_in[12];
    float* out = (float*)d_out;

    const int* src = ei;
    const int* dst = ei + NE;

    float* p_h;
    uint32_t* p_outh;
    uint32_t* p_outl;
    uint32_t* p_Wph;
    uint32_t* p_Wpl;
    cudaGetSymbolAddress((void**)&p_h, g_h);
    cudaGetSymbolAddress((void**)&p_outh, g_outh);
    cudaGetSymbolAddress((void**)&p_outl, g_outl);
    cudaGetSymbolAddress((void**)&p_Wph, g_Wph);
    cudaGetSymbolAddress((void**)&p_Wpl, g_Wpl);

    cudaFuncSetAttribute(k_gemm_bf, cudaFuncAttributeMaxDynamicSharedMemorySize, GSMEM);

    int gblocks = (NN + TM - 1) / TM;

    // idx 0: encoder stage 1 (independent of CSR)
    k_enc1<<<NN, 64>>>(x, Wn1, bn1);            // g_outh/l = split(relu(x@Wn1+bn1))
    // idx 1: CSR zero
    k_zero<<<(NN + 255) / 256, 256>>>();
    // idx 2: weight preconversion (needed before idx 3)
    k_prepW<<<((NL + 1) * D * D / 2 + 255) / 256, 256>>>(Wn2, Wg);
    // idx 3: encoder GEMM  <-- profiled slot
    k_gemm_bf<<<gblocks, 256, GSMEM>>>(p_outh, p_outl, p_Wph, p_Wpl, bn2, p_h, 0);
    // idx 4-8: CSR build finish
    k_hist<<<(NE + 255) / 256, 256>>>(dst);
    k_scan<<<1, 1024>>>();
    k_scatter<<<(NE + 255) / 256, 256>>>(dst);
    k_sort<<<(NN + 255) / 256, 256>>>();
    k_fill<<<(NE + 255) / 256, 256>>>(src, attr);

    // ---- 4 GENConv layers ----
    for (int l = 0; l < NL; l++) {
        k_agg<<<NN, 64>>>(We, be, l);  // g_outh/l = split(agg + g_h)
        k_gemm_bf<<<gblocks, 256, GSMEM>>>(p_outh, p_outl, p_Wph + (l + 1) * D * D / 2,
                                           p_Wpl + (l + 1) * D * D / 2, bg + l * D, p_h,
                                           l + 1);
    }

    // ---- head ----
    k_head<<<(NN * 32 + 255) / 256, 256>>>(Wo, bo, out);
}